// round 1
// baseline (speedup 1.0000x reference)
#include <cuda_runtime.h>
#include <mma.h>

using namespace nvcuda;

#define T_DIM 2048
#define B_DIM 2
#define E_DIM 1024
#define H_DIM 16
#define D_DIM 64
#define M_DIM (T_DIM * B_DIM)   // 4096 rows for projection GEMMs

// Scratch (static __device__ arrays: allocation-free per harness rules)
__device__ float g_q[B_DIM * H_DIM * T_DIM * D_DIM];   // (b,h,t,d), pre-scaled
__device__ float g_k[B_DIM * H_DIM * T_DIM * D_DIM];
__device__ float g_v[B_DIM * H_DIM * T_DIM * D_DIM];
__device__ float g_attn[T_DIM * B_DIM * E_DIM];        // (t,b,e)

// ---------------------------------------------------------------------------
// Projection GEMM: C[M=4096, N=1024] = A[M,1024] @ W[N,1024]^T + bias, * scale
// MODE 0: scatter output to (b,h,t,d) layout. MODE 1: plain (row, col).
// Block: 64x64 tile, 256 threads (8 warps, 4x2 warp grid), BK=32, tf32 wmma.
// ---------------------------------------------------------------------------
template <int MODE>
__global__ __launch_bounds__(256)
void proj_gemm_kernel(const float* __restrict__ A, const float* __restrict__ W,
                      const float* __restrict__ bias, float* __restrict__ out,
                      float scale)
{
    __shared__ float As[64][36];   // 144B rows (16B-aligned)
    __shared__ float Bs[64][36];
    __shared__ float Cs[64][68];   // 272B rows

    const int tid  = threadIdx.x;
    const int warp = tid >> 5;
    const int wm   = warp & 3;     // 4 warps along M (16 rows each)
    const int wn   = warp >> 2;    // 2 warps along N (32 cols each)
    const int row0 = blockIdx.y * 64;
    const int col0 = blockIdx.x * 64;

    wmma::fragment<wmma::accumulator, 16, 16, 8, float> acc[2];
    wmma::fill_fragment(acc[0], 0.0f);
    wmma::fill_fragment(acc[1], 0.0f);

    for (int k0 = 0; k0 < 1024; k0 += 32) {
        // Stage A tile (64x32) and W tile (64x32) with float4 loads
        #pragma unroll
        for (int i = 0; i < 2; i++) {
            int idx = tid + i * 256;          // 0..511
            int r   = idx >> 3;               // 0..63
            int c4  = (idx & 7) * 4;          // 0,4,..,28
            *(float4*)&As[r][c4] = *(const float4*)&A[(size_t)(row0 + r) * 1024 + k0 + c4];
            *(float4*)&Bs[r][c4] = *(const float4*)&W[(size_t)(col0 + r) * 1024 + k0 + c4];
        }
        __syncthreads();

        #pragma unroll
        for (int ks = 0; ks < 4; ks++) {
            wmma::fragment<wmma::matrix_a, 16, 16, 8, wmma::precision::tf32, wmma::row_major> a;
            wmma::load_matrix_sync(a, &As[wm * 16][ks * 8], 36);
            #pragma unroll
            for (int t = 0; t < a.num_elements; t++) a.x[t] = wmma::__float_to_tf32(a.x[t]);
            #pragma unroll
            for (int j = 0; j < 2; j++) {
                wmma::fragment<wmma::matrix_b, 16, 16, 8, wmma::precision::tf32, wmma::col_major> b;
                wmma::load_matrix_sync(b, &Bs[wn * 32 + j * 16][ks * 8], 36);
                #pragma unroll
                for (int t = 0; t < b.num_elements; t++) b.x[t] = wmma::__float_to_tf32(b.x[t]);
                wmma::mma_sync(acc[j], a, b, acc[j]);
            }
        }
        __syncthreads();
    }

    wmma::store_matrix_sync(&Cs[wm * 16][wn * 32],      acc[0], 68, wmma::mem_row_major);
    wmma::store_matrix_sync(&Cs[wm * 16][wn * 32 + 16], acc[1], 68, wmma::mem_row_major);
    __syncthreads();

    for (int idx = tid; idx < 64 * 64; idx += 256) {
        int r = idx >> 6, c = idx & 63;
        int o = col0 + c;
        float v = (Cs[r][c] + bias[o]) * scale;
        int grow = row0 + r;                 // = t*B + b
        if (MODE == 0) {
            int t = grow >> 1, b = grow & 1;
            int h = o >> 6, d = o & 63;
            out[(((size_t)(b * H_DIM + h)) * T_DIM + t) * D_DIM + d] = v;
        } else {
            out[(size_t)grow * E_DIM + o] = v;
        }
    }
}

// ---------------------------------------------------------------------------
// Flash attention: one block per (bh, 64-query tile). 256 threads, 8 warps.
// Dynamic smem: Qs,Ks,Vs,Ss,Os each [64][68] fp32 = 87040 bytes.
// ---------------------------------------------------------------------------
__global__ __launch_bounds__(256)
void attn_kernel(const float* __restrict__ q, const float* __restrict__ k,
                 const float* __restrict__ v, const unsigned char* __restrict__ mask,
                 float* __restrict__ out)
{
    extern __shared__ float sm[];
    float (*Qs)[68] = (float (*)[68])(sm);
    float (*Ks)[68] = (float (*)[68])(sm + 1 * 64 * 68);
    float (*Vs)[68] = (float (*)[68])(sm + 2 * 64 * 68);
    float (*Ss)[68] = (float (*)[68])(sm + 3 * 64 * 68);
    float (*Os)[68] = (float (*)[68])(sm + 4 * 64 * 68);

    const int tid  = threadIdx.x;
    const int warp = tid >> 5;
    const int wm   = warp & 3;
    const int wn   = warp >> 2;
    const int qt0  = blockIdx.x * 64;
    const int bh   = blockIdx.y;
    const int b    = bh / H_DIM;
    const int h    = bh % H_DIM;

    const float* qb = q + (size_t)bh * T_DIM * D_DIM;
    const float* kb = k + (size_t)bh * T_DIM * D_DIM;
    const float* vb = v + (size_t)bh * T_DIM * D_DIM;

    // Load Q tile, zero O
    for (int i = tid; i < 64 * 16; i += 256) {
        int r = i >> 4, c4 = (i & 15) * 4;
        *(float4*)&Qs[r][c4] = *(const float4*)&qb[(size_t)(qt0 + r) * 64 + c4];
    }
    for (int i = tid; i < 64 * 64; i += 256) Os[i >> 6][i & 63] = 0.0f;

    const int myrow = tid >> 2;   // 0..63 (4 threads per row)
    const int sub   = tid & 3;
    float m_r = -1e30f, l_r = 0.0f;

    __syncthreads();

    for (int st = 0; st < 32; st++) {
        const int s0 = st * 64;
        // Stage K, V tiles
        for (int i = tid; i < 64 * 16; i += 256) {
            int r = i >> 4, c4 = (i & 15) * 4;
            *(float4*)&Ks[r][c4] = *(const float4*)&kb[(size_t)(s0 + r) * 64 + c4];
            *(float4*)&Vs[r][c4] = *(const float4*)&vb[(size_t)(s0 + r) * 64 + c4];
        }
        __syncthreads();

        // S = Q @ K^T (64x64x64)
        {
            wmma::fragment<wmma::accumulator, 16, 16, 8, float> sacc[2];
            wmma::fill_fragment(sacc[0], 0.0f);
            wmma::fill_fragment(sacc[1], 0.0f);
            #pragma unroll
            for (int kd = 0; kd < 8; kd++) {
                wmma::fragment<wmma::matrix_a, 16, 16, 8, wmma::precision::tf32, wmma::row_major> a;
                wmma::load_matrix_sync(a, &Qs[wm * 16][kd * 8], 68);
                #pragma unroll
                for (int t = 0; t < a.num_elements; t++) a.x[t] = wmma::__float_to_tf32(a.x[t]);
                #pragma unroll
                for (int j = 0; j < 2; j++) {
                    wmma::fragment<wmma::matrix_b, 16, 16, 8, wmma::precision::tf32, wmma::col_major> bb;
                    wmma::load_matrix_sync(bb, &Ks[wn * 32 + j * 16][kd * 8], 68);
                    #pragma unroll
                    for (int t = 0; t < bb.num_elements; t++) bb.x[t] = wmma::__float_to_tf32(bb.x[t]);
                    wmma::mma_sync(sacc[j], a, bb, sacc[j]);
                }
            }
            wmma::store_matrix_sync(&Ss[wm * 16][wn * 32],      sacc[0], 68, wmma::mem_row_major);
            wmma::store_matrix_sync(&Ss[wm * 16][wn * 32 + 16], sacc[1], 68, wmma::mem_row_major);
        }
        __syncthreads();

        // Online softmax (fp32), 4 threads per row, 16 cols each
        {
            float sv[16];
            float vmax = -1e30f;
            #pragma unroll
            for (int i = 0; i < 16; i++) {
                int c = sub * 16 + i;
                float s = Ss[myrow][c];
                if (mask[(size_t)b * T_DIM + s0 + c]) s = -1e30f;
                sv[i] = s;
                vmax  = fmaxf(vmax, s);
            }
            vmax = fmaxf(vmax, __shfl_xor_sync(0xffffffffu, vmax, 1));
            vmax = fmaxf(vmax, __shfl_xor_sync(0xffffffffu, vmax, 2));
            float m_new = fmaxf(m_r, vmax);
            float alpha = __expf(m_r - m_new);
            float sum = 0.0f;
            #pragma unroll
            for (int i = 0; i < 16; i++) {
                float p = (sv[i] <= -1e29f) ? 0.0f : __expf(sv[i] - m_new);
                Ss[myrow][sub * 16 + i] = p;
                sum += p;
            }
            sum += __shfl_xor_sync(0xffffffffu, sum, 1);
            sum += __shfl_xor_sync(0xffffffffu, sum, 2);
            l_r = l_r * alpha + sum;
            m_r = m_new;
            #pragma unroll
            for (int i = 0; i < 16; i++) Os[myrow][sub * 16 + i] *= alpha;
        }
        __syncthreads();

        // O += P @ V (64x64x64)
        {
            wmma::fragment<wmma::accumulator, 16, 16, 8, float> oacc[2];
            wmma::load_matrix_sync(oacc[0], &Os[wm * 16][wn * 32],      68, wmma::mem_row_major);
            wmma::load_matrix_sync(oacc[1], &Os[wm * 16][wn * 32 + 16], 68, wmma::mem_row_major);
            #pragma unroll
            for (int ks = 0; ks < 8; ks++) {
                wmma::fragment<wmma::matrix_a, 16, 16, 8, wmma::precision::tf32, wmma::row_major> a;
                wmma::load_matrix_sync(a, &Ss[wm * 16][ks * 8], 68);
                #pragma unroll
                for (int t = 0; t < a.num_elements; t++) a.x[t] = wmma::__float_to_tf32(a.x[t]);
                #pragma unroll
                for (int j = 0; j < 2; j++) {
                    wmma::fragment<wmma::matrix_b, 16, 16, 8, wmma::precision::tf32, wmma::row_major> bb;
                    wmma::load_matrix_sync(bb, &Vs[ks * 8][wn * 32 + j * 16], 68);
                    #pragma unroll
                    for (int t = 0; t < bb.num_elements; t++) bb.x[t] = wmma::__float_to_tf32(bb.x[t]);
                    wmma::mma_sync(oacc[j], a, bb, oacc[j]);
                }
            }
            wmma::store_matrix_sync(&Os[wm * 16][wn * 32],      oacc[0], 68, wmma::mem_row_major);
            wmma::store_matrix_sync(&Os[wm * 16][wn * 32 + 16], oacc[1], 68, wmma::mem_row_major);
        }
        __syncthreads();
    }

    // Epilogue: out[(t,b), h*64 + d] = O / l
    {
        float invl = (l_r > 0.0f) ? (1.0f / l_r) : 0.0f;
        int t = qt0 + myrow;
        float* dst = out + ((size_t)t * B_DIM + b) * E_DIM + h * D_DIM;
        #pragma unroll
        for (int i = 0; i < 16; i++) dst[sub * 16 + i] = Os[myrow][sub * 16 + i] * invl;
    }
}

// ---------------------------------------------------------------------------
extern "C" void kernel_launch(void* const* d_in, const int* in_sizes, int n_in,
                              void* d_out, int out_size)
{
    (void)in_sizes; (void)n_in; (void)out_size;
    const float* query = (const float*)d_in[0];
    const float* key   = (const float*)d_in[1];
    const float* value = (const float*)d_in[2];
    const unsigned char* mask = (const unsigned char*)d_in[3];
    const float* wq = (const float*)d_in[4];
    const float* bq = (const float*)d_in[5];
    const float* wk = (const float*)d_in[6];
    const float* bk = (const float*)d_in[7];
    const float* wv = (const float*)d_in[8];
    const float* bv = (const float*)d_in[9];
    const float* wo = (const float*)d_in[10];
    const float* bo = (const float*)d_in[11];
    float* out = (float*)d_out;

    float *qb, *kb, *vb, *ab;
    cudaGetSymbolAddress((void**)&qb, g_q);
    cudaGetSymbolAddress((void**)&kb, g_k);
    cudaGetSymbolAddress((void**)&vb, g_v);
    cudaGetSymbolAddress((void**)&ab, g_attn);

    const float scaling = 0.125f;   // D^-0.5, D=64

    dim3 gproj(E_DIM / 64, M_DIM / 64);   // (16, 64)
    proj_gemm_kernel<0><<<gproj, 256>>>(query, wq, bq, qb, scaling);
    proj_gemm_kernel<0><<<gproj, 256>>>(key,   wk, bk, kb, 1.0f);
    proj_gemm_kernel<0><<<gproj, 256>>>(value, wv, bv, vb, 1.0f);

    static int smem_set = 0;
    const int attn_smem = 5 * 64 * 68 * (int)sizeof(float);   // 87040
    if (!smem_set) {
        cudaFuncSetAttribute(attn_kernel, cudaFuncAttributeMaxDynamicSharedMemorySize, attn_smem);
        smem_set = 1;
    }
    dim3 gattn(T_DIM / 64, B_DIM * H_DIM);   // (32, 32)
    attn_kernel<<<gattn, 256, attn_smem>>>(qb, kb, vb, mask, ab);

    proj_gemm_kernel<1><<<gproj, 256>>>(ab, wo, bo, out, 1.0f);
}

// round 2
// speedup vs baseline: 1.6856x; 1.6856x over previous
#include <cuda_runtime.h>
#include <mma.h>

using namespace nvcuda;

#define T_DIM 2048
#define B_DIM 2
#define E_DIM 1024
#define H_DIM 16
#define D_DIM 64
#define M_DIM (T_DIM * B_DIM)

// Scratch (static __device__ arrays: allocation-free per harness rules)
__device__ float g_q[B_DIM * H_DIM * T_DIM * D_DIM];   // (b,h,t,d), pre-scaled, tf32-rounded
__device__ float g_k[B_DIM * H_DIM * T_DIM * D_DIM];
__device__ float g_v[B_DIM * H_DIM * T_DIM * D_DIM];
__device__ float g_attn[T_DIM * B_DIM * E_DIM];        // (t,b,e)
__device__ float g_bias[B_DIM * T_DIM];                // 0 or -1e30 per key

__device__ __forceinline__ unsigned f2tf(float x) {
    unsigned u;
    asm("cvt.rna.tf32.f32 %0, %1;" : "=r"(u) : "f"(x));
    return u;
}

__device__ __forceinline__ void mma8(float* d, const unsigned* a, unsigned b0, unsigned b1) {
    asm volatile(
        "mma.sync.aligned.m16n8k8.row.col.f32.tf32.tf32.f32 "
        "{%0,%1,%2,%3},{%4,%5,%6,%7},{%8,%9},{%0,%1,%2,%3};"
        : "+f"(d[0]), "+f"(d[1]), "+f"(d[2]), "+f"(d[3])
        : "r"(a[0]), "r"(a[1]), "r"(a[2]), "r"(a[3]), "r"(b0), "r"(b1));
}

// ---------------------------------------------------------------------------
// mask -> additive bias
// ---------------------------------------------------------------------------
__global__ void mask_bias_kernel(const unsigned char* __restrict__ mask, float* __restrict__ bias) {
    int i = blockIdx.x * blockDim.x + threadIdx.x;
    if (i < B_DIM * T_DIM) bias[i] = mask[i] ? -1e30f : 0.0f;
}

// ---------------------------------------------------------------------------
// Projection GEMM: C[M,1024] = A[M,1024] @ W[1024,1024]^T + bias, * scale
// Block tile 128x64, 256 threads (8 warps: 4 along M x 2 along N), BK=32.
// MODE 0: scatter to (b,h,t,d) + tf32 round. MODE 1: plain (row,col) fp32.
// ---------------------------------------------------------------------------
template <int MODE>
__global__ __launch_bounds__(256)
void proj_gemm_kernel(const float* __restrict__ A, const float* __restrict__ W,
                      const float* __restrict__ bias, float* __restrict__ out,
                      float scale)
{
    __shared__ float smbuf[128 * 68];                  // 34816 B, aliased
    float (*As)[36] = (float (*)[36])smbuf;            // 128 x 36
    float (*Bs)[36] = (float (*)[36])(smbuf + 128 * 36);  // 64 x 36
    float (*Cs)[68] = (float (*)[68])smbuf;            // 128 x 68 (epilogue alias)

    const int tid  = threadIdx.x;
    const int warp = tid >> 5;
    const int wm   = warp & 3;     // 4 warps along M (32 rows each)
    const int wn   = warp >> 2;    // 2 warps along N (32 cols each)
    const int row0 = blockIdx.y * 128;
    const int col0 = blockIdx.x * 64;

    wmma::fragment<wmma::accumulator, 16, 16, 8, float> acc[2][2];
    #pragma unroll
    for (int ms = 0; ms < 2; ms++)
        #pragma unroll
        for (int ns = 0; ns < 2; ns++)
            wmma::fill_fragment(acc[ms][ns], 0.0f);

    for (int k0 = 0; k0 < 1024; k0 += 32) {
        // Stage A (128x32): 1024 float4 / 256 thr = 4 each
        #pragma unroll
        for (int i = 0; i < 4; i++) {
            int idx = tid + i * 256;
            int r = idx >> 3, c4 = (idx & 7) * 4;
            *(float4*)&As[r][c4] = *(const float4*)&A[(size_t)(row0 + r) * 1024 + k0 + c4];
        }
        // Stage W (64x32): 512 float4 / 256 = 2 each
        #pragma unroll
        for (int i = 0; i < 2; i++) {
            int idx = tid + i * 256;
            int r = idx >> 3, c4 = (idx & 7) * 4;
            *(float4*)&Bs[r][c4] = *(const float4*)&W[(size_t)(col0 + r) * 1024 + k0 + c4];
        }
        __syncthreads();

        #pragma unroll
        for (int ks = 0; ks < 4; ks++) {
            wmma::fragment<wmma::matrix_a, 16, 16, 8, wmma::precision::tf32, wmma::row_major> a[2];
            wmma::fragment<wmma::matrix_b, 16, 16, 8, wmma::precision::tf32, wmma::col_major> b[2];
            #pragma unroll
            for (int ms = 0; ms < 2; ms++) {
                wmma::load_matrix_sync(a[ms], &As[wm * 32 + ms * 16][ks * 8], 36);
                #pragma unroll
                for (int t = 0; t < a[ms].num_elements; t++) a[ms].x[t] = wmma::__float_to_tf32(a[ms].x[t]);
            }
            #pragma unroll
            for (int ns = 0; ns < 2; ns++) {
                wmma::load_matrix_sync(b[ns], &Bs[wn * 32 + ns * 16][ks * 8], 36);
                #pragma unroll
                for (int t = 0; t < b[ns].num_elements; t++) b[ns].x[t] = wmma::__float_to_tf32(b[ns].x[t]);
            }
            #pragma unroll
            for (int ms = 0; ms < 2; ms++)
                #pragma unroll
                for (int ns = 0; ns < 2; ns++)
                    wmma::mma_sync(acc[ms][ns], a[ms], b[ns], acc[ms][ns]);
        }
        __syncthreads();
    }

    // Epilogue via aliased smem
    #pragma unroll
    for (int ms = 0; ms < 2; ms++)
        #pragma unroll
        for (int ns = 0; ns < 2; ns++)
            wmma::store_matrix_sync(&Cs[wm * 32 + ms * 16][wn * 32 + ns * 16], acc[ms][ns], 68,
                                    wmma::mem_row_major);
    __syncthreads();

    for (int idx = tid; idx < 128 * 64; idx += 256) {
        int r = idx >> 6, c = idx & 63;
        int o = col0 + c;
        float v = (Cs[r][c] + bias[o]) * scale;
        int grow = row0 + r;               // = t*B + b
        if (MODE == 0) {
            v = __uint_as_float(f2tf(v));  // pre-round to tf32 for the attention mmas
            int t = grow >> 1, b = grow & 1;
            int h = o >> 6, d = o & 63;
            out[(((size_t)(b * H_DIM + h)) * T_DIM + t) * D_DIM + d] = v;
        } else {
            out[(size_t)grow * E_DIM + o] = v;
        }
    }
}

// ---------------------------------------------------------------------------
// Flash attention, raw mma m16n8k8 tf32, register-resident O + softmax state.
// Block: 128 threads (4 warps), 64 queries x 64 keys per tile, D=64.
// ---------------------------------------------------------------------------
#define PADK 68
#define PADV 72
#define PADP 68

__global__ __launch_bounds__(128)
void attn_kernel(const float* __restrict__ q, const float* __restrict__ k,
                 const float* __restrict__ v, const float* __restrict__ biasg,
                 float* __restrict__ out)
{
    extern __shared__ float sm[];
    float (*Ks)[PADK] = (float (*)[PADK])sm;                       // 64 x 68
    float (*Vs)[PADV] = (float (*)[PADV])(sm + 64 * PADK);         // 64 x 72
    float* Ps = sm + 64 * PADK + 64 * PADV;                        // 4 warps x 16 x 68
    float* Bb = Ps + 4 * 16 * PADP;                                // 64 floats

    const int tid  = threadIdx.x;
    const int warp = tid >> 5;
    const int lane = tid & 31;
    const int g    = lane >> 2;    // groupID (row within 16-row warp tile)
    const int tig  = lane & 3;     // thread-in-group
    const int qt0  = blockIdx.x * 64;
    const int bh   = blockIdx.y;
    const int b    = bh >> 4;
    const int h    = bh & 15;

    const float* qb = q + (size_t)bh * T_DIM * D_DIM;
    const float* kb = k + (size_t)bh * T_DIM * D_DIM;
    const float* vb = v + (size_t)bh * T_DIM * D_DIM;
    float* Pw = Ps + warp * 16 * PADP;

    // --- Load Q tile for this warp into A fragments (via per-warp smem stage)
    unsigned qa[8][4];
    {
        const float* qrow = qb + (size_t)(qt0 + warp * 16) * 64;
        for (int i = lane; i < 16 * 16; i += 32) {
            int r = i >> 4, c4 = (i & 15) * 4;
            *(float4*)&Pw[r * PADP + c4] = *(const float4*)&qrow[r * 64 + c4];
        }
        __syncwarp();
        #pragma unroll
        for (int kc = 0; kc < 8; kc++) {
            qa[kc][0] = __float_as_uint(Pw[g * PADP + kc * 8 + tig]);
            qa[kc][1] = __float_as_uint(Pw[(g + 8) * PADP + kc * 8 + tig]);
            qa[kc][2] = __float_as_uint(Pw[g * PADP + kc * 8 + tig + 4]);
            qa[kc][3] = __float_as_uint(Pw[(g + 8) * PADP + kc * 8 + tig + 4]);
        }
        __syncwarp();
    }

    float o[8][4];
    #pragma unroll
    for (int j = 0; j < 8; j++) { o[j][0] = o[j][1] = o[j][2] = o[j][3] = 0.0f; }
    float m0 = -1e30f, m1 = -1e30f, l0 = 0.0f, l1 = 0.0f;

    for (int st = 0; st < 32; st++) {
        const int s0 = st * 64;
        // Stage K, V tiles (all 128 threads, float4)
        for (int i = tid; i < 64 * 16; i += 128) {
            int r = i >> 4, c4 = (i & 15) * 4;
            *(float4*)&Ks[r][c4] = *(const float4*)&kb[(size_t)(s0 + r) * 64 + c4];
            *(float4*)&Vs[r][c4] = *(const float4*)&vb[(size_t)(s0 + r) * 64 + c4];
        }
        if (tid < 64) Bb[tid] = biasg[(size_t)b * T_DIM + s0 + tid];
        __syncthreads();

        // --- S = Q @ K^T : 8 n-tiles of 8 keys, k over 8 d-chunks
        float s[8][4];
        #pragma unroll
        for (int j = 0; j < 8; j++) { s[j][0] = s[j][1] = s[j][2] = s[j][3] = 0.0f; }
        #pragma unroll
        for (int kc = 0; kc < 8; kc++) {
            #pragma unroll
            for (int j = 0; j < 8; j++) {
                unsigned b0 = __float_as_uint(Ks[j * 8 + g][kc * 8 + tig]);
                unsigned b1 = __float_as_uint(Ks[j * 8 + g][kc * 8 + tig + 4]);
                mma8(s[j], qa[kc], b0, b1);
            }
        }

        // --- Online softmax on register fragments
        float vmax0 = -1e30f, vmax1 = -1e30f;
        #pragma unroll
        for (int j = 0; j < 8; j++) {
            float b0v = Bb[j * 8 + 2 * tig], b1v = Bb[j * 8 + 2 * tig + 1];
            s[j][0] += b0v; s[j][1] += b1v; s[j][2] += b0v; s[j][3] += b1v;
            vmax0 = fmaxf(vmax0, fmaxf(s[j][0], s[j][1]));
            vmax1 = fmaxf(vmax1, fmaxf(s[j][2], s[j][3]));
        }
        vmax0 = fmaxf(vmax0, __shfl_xor_sync(0xffffffffu, vmax0, 1));
        vmax0 = fmaxf(vmax0, __shfl_xor_sync(0xffffffffu, vmax0, 2));
        vmax1 = fmaxf(vmax1, __shfl_xor_sync(0xffffffffu, vmax1, 1));
        vmax1 = fmaxf(vmax1, __shfl_xor_sync(0xffffffffu, vmax1, 2));
        float m0n = fmaxf(m0, vmax0), m1n = fmaxf(m1, vmax1);
        float al0 = __expf(m0 - m0n), al1 = __expf(m1 - m1n);
        float sum0 = 0.0f, sum1 = 0.0f;
        #pragma unroll
        for (int j = 0; j < 8; j++) {
            s[j][0] = __expf(s[j][0] - m0n); sum0 += s[j][0];
            s[j][1] = __expf(s[j][1] - m0n); sum0 += s[j][1];
            s[j][2] = __expf(s[j][2] - m1n); sum1 += s[j][2];
            s[j][3] = __expf(s[j][3] - m1n); sum1 += s[j][3];
        }
        sum0 += __shfl_xor_sync(0xffffffffu, sum0, 1);
        sum0 += __shfl_xor_sync(0xffffffffu, sum0, 2);
        sum1 += __shfl_xor_sync(0xffffffffu, sum1, 1);
        sum1 += __shfl_xor_sync(0xffffffffu, sum1, 2);
        l0 = l0 * al0 + sum0; m0 = m0n;
        l1 = l1 * al1 + sum1; m1 = m1n;
        #pragma unroll
        for (int j = 0; j < 8; j++) {
            o[j][0] *= al0; o[j][1] *= al0; o[j][2] *= al1; o[j][3] *= al1;
        }

        // --- P: acc layout -> A layout via per-warp smem (warp-private, syncwarp only)
        #pragma unroll
        for (int j = 0; j < 8; j++) {
            *(float2*)&Pw[g * PADP + j * 8 + 2 * tig] =
                make_float2(__uint_as_float(f2tf(s[j][0])), __uint_as_float(f2tf(s[j][1])));
            *(float2*)&Pw[(g + 8) * PADP + j * 8 + 2 * tig] =
                make_float2(__uint_as_float(f2tf(s[j][2])), __uint_as_float(f2tf(s[j][3])));
        }
        __syncwarp();

        // --- O += P @ V : k over 8 key-chunks, 8 d-tiles
        #pragma unroll
        for (int kc = 0; kc < 8; kc++) {
            unsigned pa[4];
            pa[0] = __float_as_uint(Pw[g * PADP + kc * 8 + tig]);
            pa[1] = __float_as_uint(Pw[(g + 8) * PADP + kc * 8 + tig]);
            pa[2] = __float_as_uint(Pw[g * PADP + kc * 8 + tig + 4]);
            pa[3] = __float_as_uint(Pw[(g + 8) * PADP + kc * 8 + tig + 4]);
            #pragma unroll
            for (int j = 0; j < 8; j++) {
                unsigned b0 = __float_as_uint(Vs[kc * 8 + tig][j * 8 + g]);
                unsigned b1 = __float_as_uint(Vs[kc * 8 + tig + 4][j * 8 + g]);
                mma8(o[j], pa, b0, b1);
            }
        }
        __syncthreads();   // Ks/Vs reuse next iteration; also covers Pw reuse
    }

    // --- Epilogue: out[(t,b), h*64 + d] = O / l
    float i0 = (l0 > 0.0f) ? 1.0f / l0 : 0.0f;
    float i1 = (l1 > 0.0f) ? 1.0f / l1 : 0.0f;
    int t0 = qt0 + warp * 16 + g;
    int t1 = t0 + 8;
    float* d0 = out + ((size_t)t0 * B_DIM + b) * E_DIM + h * 64;
    float* d1 = out + ((size_t)t1 * B_DIM + b) * E_DIM + h * 64;
    #pragma unroll
    for (int j = 0; j < 8; j++) {
        *(float2*)&d0[j * 8 + 2 * tig] = make_float2(o[j][0] * i0, o[j][1] * i0);
        *(float2*)&d1[j * 8 + 2 * tig] = make_float2(o[j][2] * i1, o[j][3] * i1);
    }
}

// ---------------------------------------------------------------------------
extern "C" void kernel_launch(void* const* d_in, const int* in_sizes, int n_in,
                              void* d_out, int out_size)
{
    (void)in_sizes; (void)n_in; (void)out_size;
    const float* query = (const float*)d_in[0];
    const float* key   = (const float*)d_in[1];
    const float* value = (const float*)d_in[2];
    const unsigned char* mask = (const unsigned char*)d_in[3];
    const float* wq = (const float*)d_in[4];
    const float* bq = (const float*)d_in[5];
    const float* wk = (const float*)d_in[6];
    const float* bk = (const float*)d_in[7];
    const float* wv = (const float*)d_in[8];
    const float* bv = (const float*)d_in[9];
    const float* wo = (const float*)d_in[10];
    const float* bo = (const float*)d_in[11];
    float* out = (float*)d_out;

    float *qb, *kb, *vb, *ab, *bb;
    cudaGetSymbolAddress((void**)&qb, g_q);
    cudaGetSymbolAddress((void**)&kb, g_k);
    cudaGetSymbolAddress((void**)&vb, g_v);
    cudaGetSymbolAddress((void**)&ab, g_attn);
    cudaGetSymbolAddress((void**)&bb, g_bias);

    const float scaling = 0.125f;   // D^-0.5, D=64

    mask_bias_kernel<<<(B_DIM * T_DIM + 255) / 256, 256>>>(mask, bb);

    dim3 gproj(E_DIM / 64, M_DIM / 128);   // (16, 32)
    proj_gemm_kernel<0><<<gproj, 256>>>(query, wq, bq, qb, scaling);
    proj_gemm_kernel<0><<<gproj, 256>>>(key,   wk, bk, kb, 1.0f);
    proj_gemm_kernel<0><<<gproj, 256>>>(value, wv, bv, vb, 1.0f);

    static int smem_set = 0;
    const int attn_smem = (64 * PADK + 64 * PADV + 4 * 16 * PADP + 64) * (int)sizeof(float);
    if (!smem_set) {
        cudaFuncSetAttribute(attn_kernel, cudaFuncAttributeMaxDynamicSharedMemorySize, attn_smem);
        smem_set = 1;
    }
    dim3 gattn(T_DIM / 64, B_DIM * H_DIM);   // (32, 32)
    attn_kernel<<<gattn, 128, attn_smem>>>(qb, kb, vb, bb, ab);

    proj_gemm_kernel<1><<<gproj, 256>>>(ab, wo, bo, out, 1.0f);
}

// round 3
// speedup vs baseline: 1.9100x; 1.1331x over previous
#include <cuda_runtime.h>
#include <mma.h>

using namespace nvcuda;

#define T_DIM 2048
#define B_DIM 2
#define E_DIM 1024
#define H_DIM 16
#define D_DIM 64
#define M_DIM (T_DIM * B_DIM)

// Scratch (static __device__ arrays: allocation-free per harness rules)
__device__ float g_q[B_DIM * H_DIM * T_DIM * D_DIM];
__device__ float g_k[B_DIM * H_DIM * T_DIM * D_DIM];
__device__ float g_v[B_DIM * H_DIM * T_DIM * D_DIM];
__device__ float g_attn[T_DIM * B_DIM * E_DIM];
__device__ float g_bias[B_DIM * T_DIM];
__device__ float g_in_r[3 * M_DIM * E_DIM];   // tf32-rounded query|key|value
__device__ float g_w_r[4 * E_DIM * E_DIM];    // tf32-rounded wq|wk|wv|wo

__device__ __forceinline__ unsigned f2tf(float x) {
    unsigned u;
    asm("cvt.rna.tf32.f32 %0, %1;" : "=r"(u) : "f"(x));
    return u;
}
__device__ __forceinline__ float f2tff(float x) { return __uint_as_float(f2tf(x)); }

__device__ __forceinline__ void cp16(float* smem, const float* gmem) {
    unsigned s = (unsigned)__cvta_generic_to_shared(smem);
    asm volatile("cp.async.cg.shared.global [%0], [%1], 16;\n" :: "r"(s), "l"(gmem));
}
__device__ __forceinline__ void cp_commit() { asm volatile("cp.async.commit_group;\n"); }
template <int N> __device__ __forceinline__ void cp_wait() {
    asm volatile("cp.async.wait_group %0;\n" :: "n"(N));
}

__device__ __forceinline__ void mma8(float* d, const unsigned* a, unsigned b0, unsigned b1) {
    asm volatile(
        "mma.sync.aligned.m16n8k8.row.col.f32.tf32.tf32.f32 "
        "{%0,%1,%2,%3},{%4,%5,%6,%7},{%8,%9},{%0,%1,%2,%3};"
        : "+f"(d[0]), "+f"(d[1]), "+f"(d[2]), "+f"(d[3])
        : "r"(a[0]), "r"(a[1]), "r"(a[2]), "r"(a[3]), "r"(b0), "r"(b1));
}

// ---------------------------------------------------------------------------
// Pre-round all GEMM operands to tf32 (rna). 4M float4 total.
// dst layout: g_in_r = [query | key | value], g_w_r = [wq | wk | wv | wo]
// ---------------------------------------------------------------------------
__global__ void preround_kernel(const float4* __restrict__ q, const float4* __restrict__ k,
                                const float4* __restrict__ v, const float4* __restrict__ wq,
                                const float4* __restrict__ wk, const float4* __restrict__ wv,
                                const float4* __restrict__ wo, float4* __restrict__ din,
                                float4* __restrict__ dw)
{
    const int IN4 = M_DIM * E_DIM / 4;   // 1048576
    const int W4  = E_DIM * E_DIM / 4;   // 262144
    int i = blockIdx.x * blockDim.x + threadIdx.x;
    const float4* s;
    float4* d;
    if (i < 3 * IN4) {
        s = (i < IN4) ? q + i : (i < 2 * IN4 ? k + (i - IN4) : v + (i - 2 * IN4));
        d = din + i;
    } else {
        int j = i - 3 * IN4;
        s = (j < W4) ? wq + j : j < 2 * W4 ? wk + (j - W4) : j < 3 * W4 ? wv + (j - 2 * W4)
                                                                        : wo + (j - 3 * W4);
        d = dw + j;
    }
    float4 x = *s;
    x.x = f2tff(x.x); x.y = f2tff(x.y); x.z = f2tff(x.z); x.w = f2tff(x.w);
    *d = x;
}

__global__ void mask_bias_kernel(const unsigned char* __restrict__ mask, float* __restrict__ bias) {
    int i = blockIdx.x * blockDim.x + threadIdx.x;
    if (i < B_DIM * T_DIM) bias[i] = mask[i] ? -1e30f : 0.0f;
}

// ---------------------------------------------------------------------------
// GEMM: C[M,1024] = A[M,1024] @ W[1024,1024]^T + bias, * scale
// 128x128 block tile, BK=32, 256 threads (4x2 warps, warp tile 32x64),
// cp.async double-buffered smem, tf32 wmma with NO in-loop conversion
// (inputs pre-rounded). MODE 0: z picks QKV set, scatter to (b,h,t,d) + round.
// MODE 1: plain fp32 output.
// ---------------------------------------------------------------------------
struct GemmArgs {
    const float* A[3];
    const float* W[3];
    const float* bias[3];
    float* out[3];
    float scale[3];
};

#define GSTRIDE 36
#define GTILE   (128 * GSTRIDE)          // floats per A or B stage tile

template <int MODE>
__global__ __launch_bounds__(256, 2)
void gemm_kernel(GemmArgs args)
{
    extern __shared__ float smem[];      // 2 stages * (A + B) = 4 * 4608 floats = 73728 B

    const int z    = (MODE == 0) ? blockIdx.z : 0;
    const float* A = args.A[z];
    const float* W = args.W[z];
    const float* bias = args.bias[z];
    float* out     = args.out[z];
    const float scale = args.scale[z];

    const int tid  = threadIdx.x;
    const int warp = tid >> 5;
    const int wm   = warp & 3;           // 4 warps along M: 32 rows each
    const int wn   = warp >> 2;          // 2 warps along N: 64 cols each
    const int row0 = blockIdx.y * 128;
    const int col0 = blockIdx.x * 128;

    const int lr  = tid >> 3;            // 0..31 ... staging row helper
    const int lc4 = (tid & 7) * 4;       // 0,4,..,28

    wmma::fragment<wmma::accumulator, 16, 16, 8, float> acc[2][4];
    #pragma unroll
    for (int mi = 0; mi < 2; mi++)
        #pragma unroll
        for (int ni = 0; ni < 4; ni++)
            wmma::fill_fragment(acc[mi][ni], 0.0f);

    // stage tile kt into buffer st
    auto stage = [&](int kt, int st) {
        float* As = smem + st * 2 * GTILE;
        float* Bs = As + GTILE;
        const int k0 = kt * 32;
        #pragma unroll
        for (int i = 0; i < 4; i++) {
            int r = lr + i * 32;
            cp16(&As[r * GSTRIDE + lc4], &A[(size_t)(row0 + r) * 1024 + k0 + lc4]);
            cp16(&Bs[r * GSTRIDE + lc4], &W[(size_t)(col0 + r) * 1024 + k0 + lc4]);
        }
        cp_commit();
    };

    stage(0, 0);
    const int NT = 1024 / 32;            // 32
    for (int t = 0; t < NT; t++) {
        if (t + 1 < NT) { stage(t + 1, (t + 1) & 1); cp_wait<1>(); }
        else            { cp_wait<0>(); }
        __syncthreads();

        float* As = smem + (t & 1) * 2 * GTILE;
        float* Bs = As + GTILE;
        #pragma unroll
        for (int ks = 0; ks < 4; ks++) {
            wmma::fragment<wmma::matrix_a, 16, 16, 8, wmma::precision::tf32, wmma::row_major> a[2];
            wmma::fragment<wmma::matrix_b, 16, 16, 8, wmma::precision::tf32, wmma::col_major> b[4];
            #pragma unroll
            for (int mi = 0; mi < 2; mi++)
                wmma::load_matrix_sync(a[mi], &As[(wm * 32 + mi * 16) * GSTRIDE + ks * 8], GSTRIDE);
            #pragma unroll
            for (int ni = 0; ni < 4; ni++)
                wmma::load_matrix_sync(b[ni], &Bs[(wn * 64 + ni * 16) * GSTRIDE + ks * 8], GSTRIDE);
            #pragma unroll
            for (int mi = 0; mi < 2; mi++)
                #pragma unroll
                for (int ni = 0; ni < 4; ni++)
                    wmma::mma_sync(acc[mi][ni], a[mi], b[ni], acc[mi][ni]);
        }
        __syncthreads();
    }

    // Epilogue via aliased smem: 128 x 132
    float* Cs = smem;
    #pragma unroll
    for (int mi = 0; mi < 2; mi++)
        #pragma unroll
        for (int ni = 0; ni < 4; ni++)
            wmma::store_matrix_sync(&Cs[(wm * 32 + mi * 16) * 132 + wn * 64 + ni * 16],
                                    acc[mi][ni], 132, wmma::mem_row_major);
    __syncthreads();

    for (int idx = tid; idx < 128 * 128; idx += 256) {
        int r = idx >> 7, c = idx & 127;
        int o = col0 + c;
        float v = (Cs[r * 132 + c] + bias[o]) * scale;
        int grow = row0 + r;                 // = t*B + b
        if (MODE == 0) {
            v = f2tff(v);                    // attention consumes tf32 operands
            int t = grow >> 1, b = grow & 1;
            int h = o >> 6, d = o & 63;
            out[(((size_t)(b * H_DIM + h)) * T_DIM + t) * D_DIM + d] = v;
        } else {
            out[(size_t)grow * E_DIM + o] = v;
        }
    }
}

// ---------------------------------------------------------------------------
// Flash attention (unchanged structure from R2): raw mma m16n8k8 tf32,
// register-resident O + softmax state. 128 threads, 64q x 64k tiles, D=64.
// Epilogue now tf32-rounds output (feeds the out-projection).
// ---------------------------------------------------------------------------
#define PADK 68
#define PADV 72
#define PADP 68

__global__ __launch_bounds__(128)
void attn_kernel(const float* __restrict__ q, const float* __restrict__ k,
                 const float* __restrict__ v, const float* __restrict__ biasg,
                 float* __restrict__ out)
{
    extern __shared__ float sm[];
    float (*Ks)[PADK] = (float (*)[PADK])sm;
    float (*Vs)[PADV] = (float (*)[PADV])(sm + 64 * PADK);
    float* Ps = sm + 64 * PADK + 64 * PADV;
    float* Bb = Ps + 4 * 16 * PADP;

    const int tid  = threadIdx.x;
    const int warp = tid >> 5;
    const int lane = tid & 31;
    const int g    = lane >> 2;
    const int tig  = lane & 3;
    const int qt0  = blockIdx.x * 64;
    const int bh   = blockIdx.y;
    const int b    = bh >> 4;
    const int h    = bh & 15;

    const float* qb = q + (size_t)bh * T_DIM * D_DIM;
    const float* kb = k + (size_t)bh * T_DIM * D_DIM;
    const float* vb = v + (size_t)bh * T_DIM * D_DIM;
    float* Pw = Ps + warp * 16 * PADP;

    unsigned qa[8][4];
    {
        const float* qrow = qb + (size_t)(qt0 + warp * 16) * 64;
        for (int i = lane; i < 16 * 16; i += 32) {
            int r = i >> 4, c4 = (i & 15) * 4;
            *(float4*)&Pw[r * PADP + c4] = *(const float4*)&qrow[r * 64 + c4];
        }
        __syncwarp();
        #pragma unroll
        for (int kc = 0; kc < 8; kc++) {
            qa[kc][0] = __float_as_uint(Pw[g * PADP + kc * 8 + tig]);
            qa[kc][1] = __float_as_uint(Pw[(g + 8) * PADP + kc * 8 + tig]);
            qa[kc][2] = __float_as_uint(Pw[g * PADP + kc * 8 + tig + 4]);
            qa[kc][3] = __float_as_uint(Pw[(g + 8) * PADP + kc * 8 + tig + 4]);
        }
        __syncwarp();
    }

    float o[8][4];
    #pragma unroll
    for (int j = 0; j < 8; j++) { o[j][0] = o[j][1] = o[j][2] = o[j][3] = 0.0f; }
    float m0 = -1e30f, m1 = -1e30f, l0 = 0.0f, l1 = 0.0f;

    for (int st = 0; st < 32; st++) {
        const int s0 = st * 64;
        for (int i = tid; i < 64 * 16; i += 128) {
            int r = i >> 4, c4 = (i & 15) * 4;
            *(float4*)&Ks[r][c4] = *(const float4*)&kb[(size_t)(s0 + r) * 64 + c4];
            *(float4*)&Vs[r][c4] = *(const float4*)&vb[(size_t)(s0 + r) * 64 + c4];
        }
        if (tid < 64) Bb[tid] = biasg[(size_t)b * T_DIM + s0 + tid];
        __syncthreads();

        float s[8][4];
        #pragma unroll
        for (int j = 0; j < 8; j++) { s[j][0] = s[j][1] = s[j][2] = s[j][3] = 0.0f; }
        #pragma unroll
        for (int kc = 0; kc < 8; kc++) {
            #pragma unroll
            for (int j = 0; j < 8; j++) {
                unsigned b0 = __float_as_uint(Ks[j * 8 + g][kc * 8 + tig]);
                unsigned b1 = __float_as_uint(Ks[j * 8 + g][kc * 8 + tig + 4]);
                mma8(s[j], qa[kc], b0, b1);
            }
        }

        float vmax0 = -1e30f, vmax1 = -1e30f;
        #pragma unroll
        for (int j = 0; j < 8; j++) {
            float b0v = Bb[j * 8 + 2 * tig], b1v = Bb[j * 8 + 2 * tig + 1];
            s[j][0] += b0v; s[j][1] += b1v; s[j][2] += b0v; s[j][3] += b1v;
            vmax0 = fmaxf(vmax0, fmaxf(s[j][0], s[j][1]));
            vmax1 = fmaxf(vmax1, fmaxf(s[j][2], s[j][3]));
        }
        vmax0 = fmaxf(vmax0, __shfl_xor_sync(0xffffffffu, vmax0, 1));
        vmax0 = fmaxf(vmax0, __shfl_xor_sync(0xffffffffu, vmax0, 2));
        vmax1 = fmaxf(vmax1, __shfl_xor_sync(0xffffffffu, vmax1, 1));
        vmax1 = fmaxf(vmax1, __shfl_xor_sync(0xffffffffu, vmax1, 2));
        float m0n = fmaxf(m0, vmax0), m1n = fmaxf(m1, vmax1);
        float al0 = __expf(m0 - m0n), al1 = __expf(m1 - m1n);
        float sum0 = 0.0f, sum1 = 0.0f;
        #pragma unroll
        for (int j = 0; j < 8; j++) {
            s[j][0] = __expf(s[j][0] - m0n); sum0 += s[j][0];
            s[j][1] = __expf(s[j][1] - m0n); sum0 += s[j][1];
            s[j][2] = __expf(s[j][2] - m1n); sum1 += s[j][2];
            s[j][3] = __expf(s[j][3] - m1n); sum1 += s[j][3];
        }
        sum0 += __shfl_xor_sync(0xffffffffu, sum0, 1);
        sum0 += __shfl_xor_sync(0xffffffffu, sum0, 2);
        sum1 += __shfl_xor_sync(0xffffffffu, sum1, 1);
        sum1 += __shfl_xor_sync(0xffffffffu, sum1, 2);
        l0 = l0 * al0 + sum0; m0 = m0n;
        l1 = l1 * al1 + sum1; m1 = m1n;
        #pragma unroll
        for (int j = 0; j < 8; j++) {
            o[j][0] *= al0; o[j][1] *= al0; o[j][2] *= al1; o[j][3] *= al1;
        }

        #pragma unroll
        for (int j = 0; j < 8; j++) {
            *(float2*)&Pw[g * PADP + j * 8 + 2 * tig] =
                make_float2(f2tff(s[j][0]), f2tff(s[j][1]));
            *(float2*)&Pw[(g + 8) * PADP + j * 8 + 2 * tig] =
                make_float2(f2tff(s[j][2]), f2tff(s[j][3]));
        }
        __syncwarp();

        #pragma unroll
        for (int kc = 0; kc < 8; kc++) {
            unsigned pa[4];
            pa[0] = __float_as_uint(Pw[g * PADP + kc * 8 + tig]);
            pa[1] = __float_as_uint(Pw[(g + 8) * PADP + kc * 8 + tig]);
            pa[2] = __float_as_uint(Pw[g * PADP + kc * 8 + tig + 4]);
            pa[3] = __float_as_uint(Pw[(g + 8) * PADP + kc * 8 + tig + 4]);
            #pragma unroll
            for (int j = 0; j < 8; j++) {
                unsigned b0 = __float_as_uint(Vs[kc * 8 + tig][j * 8 + g]);
                unsigned b1 = __float_as_uint(Vs[kc * 8 + tig + 4][j * 8 + g]);
                mma8(o[j], pa, b0, b1);
            }
        }
        __syncthreads();
    }

    float i0 = (l0 > 0.0f) ? 1.0f / l0 : 0.0f;
    float i1 = (l1 > 0.0f) ? 1.0f / l1 : 0.0f;
    int t0 = qt0 + warp * 16 + g;
    int t1 = t0 + 8;
    float* d0 = out + ((size_t)t0 * B_DIM + b) * E_DIM + h * 64;
    float* d1 = out + ((size_t)t1 * B_DIM + b) * E_DIM + h * 64;
    #pragma unroll
    for (int j = 0; j < 8; j++) {
        *(float2*)&d0[j * 8 + 2 * tig] = make_float2(f2tff(o[j][0] * i0), f2tff(o[j][1] * i0));
        *(float2*)&d1[j * 8 + 2 * tig] = make_float2(f2tff(o[j][2] * i1), f2tff(o[j][3] * i1));
    }
}

// ---------------------------------------------------------------------------
extern "C" void kernel_launch(void* const* d_in, const int* in_sizes, int n_in,
                              void* d_out, int out_size)
{
    (void)in_sizes; (void)n_in; (void)out_size;
    const float* query = (const float*)d_in[0];
    const float* key   = (const float*)d_in[1];
    const float* value = (const float*)d_in[2];
    const unsigned char* mask = (const unsigned char*)d_in[3];
    const float* wq = (const float*)d_in[4];
    const float* bq = (const float*)d_in[5];
    const float* wk = (const float*)d_in[6];
    const float* bk = (const float*)d_in[7];
    const float* wv = (const float*)d_in[8];
    const float* bv = (const float*)d_in[9];
    const float* wo = (const float*)d_in[10];
    const float* bo = (const float*)d_in[11];
    float* out = (float*)d_out;

    float *qb, *kb, *vb, *ab, *bb, *inr, *wr;
    cudaGetSymbolAddress((void**)&qb, g_q);
    cudaGetSymbolAddress((void**)&kb, g_k);
    cudaGetSymbolAddress((void**)&vb, g_v);
    cudaGetSymbolAddress((void**)&ab, g_attn);
    cudaGetSymbolAddress((void**)&bb, g_bias);
    cudaGetSymbolAddress((void**)&inr, g_in_r);
    cudaGetSymbolAddress((void**)&wr, g_w_r);

    const int IN  = M_DIM * E_DIM;       // 4194304
    const int WSZ = E_DIM * E_DIM;       // 1048576

    static int smem_set = 0;
    const int gemm_smem = 2 * 2 * GTILE * (int)sizeof(float);   // 73728
    const int attn_smem = (64 * PADK + 64 * PADV + 4 * 16 * PADP + 64) * (int)sizeof(float);
    if (!smem_set) {
        cudaFuncSetAttribute(gemm_kernel<0>, cudaFuncAttributeMaxDynamicSharedMemorySize, gemm_smem);
        cudaFuncSetAttribute(gemm_kernel<1>, cudaFuncAttributeMaxDynamicSharedMemorySize, gemm_smem);
        cudaFuncSetAttribute(attn_kernel, cudaFuncAttributeMaxDynamicSharedMemorySize, attn_smem);
        smem_set = 1;
    }

    preround_kernel<<<(3 * IN + 4 * WSZ) / 4 / 256, 256>>>(
        (const float4*)query, (const float4*)key, (const float4*)value,
        (const float4*)wq, (const float4*)wk, (const float4*)wv, (const float4*)wo,
        (float4*)inr, (float4*)wr);

    mask_bias_kernel<<<(B_DIM * T_DIM + 255) / 256, 256>>>(mask, bb);

    GemmArgs qkv;
    qkv.A[0] = inr;           qkv.A[1] = inr + IN;      qkv.A[2] = inr + 2 * IN;
    qkv.W[0] = wr;            qkv.W[1] = wr + WSZ;      qkv.W[2] = wr + 2 * WSZ;
    qkv.bias[0] = bq;         qkv.bias[1] = bk;         qkv.bias[2] = bv;
    qkv.out[0] = qb;          qkv.out[1] = kb;          qkv.out[2] = vb;
    qkv.scale[0] = 0.125f;    qkv.scale[1] = 1.0f;      qkv.scale[2] = 1.0f;

    dim3 gqkv(E_DIM / 128, M_DIM / 128, 3);   // (8, 32, 3)
    gemm_kernel<0><<<gqkv, 256, gemm_smem>>>(qkv);

    dim3 gattn(T_DIM / 64, B_DIM * H_DIM);    // (32, 32)
    attn_kernel<<<gattn, 128, attn_smem>>>(qb, kb, vb, bb, ab);

    GemmArgs oargs;
    oargs.A[0] = ab;   oargs.W[0] = wr + 3 * WSZ;  oargs.bias[0] = bo;
    oargs.out[0] = out; oargs.scale[0] = 1.0f;
    oargs.A[1] = oargs.A[2] = ab; oargs.W[1] = oargs.W[2] = wr;
    oargs.bias[1] = oargs.bias[2] = bo; oargs.out[1] = oargs.out[2] = out;
    oargs.scale[1] = oargs.scale[2] = 1.0f;

    dim3 gop(E_DIM / 128, M_DIM / 128, 1);    // (8, 32)
    gemm_kernel<1><<<gop, 256, gemm_smem>>>(oargs);
}

// round 4
// speedup vs baseline: 1.9284x; 1.0096x over previous
#include <cuda_runtime.h>
#include <mma.h>

using namespace nvcuda;

#define T_DIM 2048
#define B_DIM 2
#define E_DIM 1024
#define H_DIM 16
#define D_DIM 64
#define M_DIM (T_DIM * B_DIM)

__device__ float g_q[B_DIM * H_DIM * T_DIM * D_DIM];
__device__ float g_k[B_DIM * H_DIM * T_DIM * D_DIM];
__device__ float g_v[B_DIM * H_DIM * T_DIM * D_DIM];
__device__ float g_attn[T_DIM * B_DIM * E_DIM];
__device__ float g_bias[B_DIM * T_DIM];
__device__ float g_in_r[3 * M_DIM * E_DIM];
__device__ float g_w_r[4 * E_DIM * E_DIM];

__device__ __forceinline__ unsigned f2tf(float x) {
    unsigned u;
    asm("cvt.rna.tf32.f32 %0, %1;" : "=r"(u) : "f"(x));
    return u;
}
__device__ __forceinline__ float f2tff(float x) { return __uint_as_float(f2tf(x)); }

__device__ __forceinline__ void cp16(float* smem, const float* gmem) {
    unsigned s = (unsigned)__cvta_generic_to_shared(smem);
    asm volatile("cp.async.cg.shared.global [%0], [%1], 16;\n" :: "r"(s), "l"(gmem));
}
__device__ __forceinline__ void cp_commit() { asm volatile("cp.async.commit_group;\n"); }
template <int N> __device__ __forceinline__ void cp_wait() {
    asm volatile("cp.async.wait_group %0;\n" :: "n"(N));
}

__device__ __forceinline__ void mma8(float* d, const unsigned* a, unsigned b0, unsigned b1) {
    asm volatile(
        "mma.sync.aligned.m16n8k8.row.col.f32.tf32.tf32.f32 "
        "{%0,%1,%2,%3},{%4,%5,%6,%7},{%8,%9},{%0,%1,%2,%3};"
        : "+f"(d[0]), "+f"(d[1]), "+f"(d[2]), "+f"(d[3])
        : "r"(a[0]), "r"(a[1]), "r"(a[2]), "r"(a[3]), "r"(b0), "r"(b1));
}

// ---------------------------------------------------------------------------
__global__ void preround_kernel(const float4* __restrict__ q, const float4* __restrict__ k,
                                const float4* __restrict__ v, const float4* __restrict__ wq,
                                const float4* __restrict__ wk, const float4* __restrict__ wv,
                                const float4* __restrict__ wo, float4* __restrict__ din,
                                float4* __restrict__ dw)
{
    const int IN4 = M_DIM * E_DIM / 4;
    const int W4  = E_DIM * E_DIM / 4;
    int i = blockIdx.x * blockDim.x + threadIdx.x;
    const float4* s;
    float4* d;
    if (i < 3 * IN4) {
        s = (i < IN4) ? q + i : (i < 2 * IN4 ? k + (i - IN4) : v + (i - 2 * IN4));
        d = din + i;
    } else {
        int j = i - 3 * IN4;
        s = (j < W4) ? wq + j : j < 2 * W4 ? wk + (j - W4) : j < 3 * W4 ? wv + (j - 2 * W4)
                                                                        : wo + (j - 3 * W4);
        d = dw + j;
    }
    float4 x = *s;
    x.x = f2tff(x.x); x.y = f2tff(x.y); x.z = f2tff(x.z); x.w = f2tff(x.w);
    *d = x;
}

__global__ void mask_bias_kernel(const unsigned char* __restrict__ mask, float* __restrict__ bias) {
    int i = blockIdx.x * blockDim.x + threadIdx.x;
    if (i < B_DIM * T_DIM) bias[i] = mask[i] ? -1e30f : 0.0f;
}

// ---------------------------------------------------------------------------
// GEMM (unchanged from R3): 128x128 tile, cp.async double buffer, tf32 wmma.
// ---------------------------------------------------------------------------
struct GemmArgs {
    const float* A[3];
    const float* W[3];
    const float* bias[3];
    float* out[3];
    float scale[3];
};

#define GSTRIDE 36
#define GTILE   (128 * GSTRIDE)

template <int MODE>
__global__ __launch_bounds__(256, 2)
void gemm_kernel(GemmArgs args)
{
    extern __shared__ float smem[];

    const int z    = (MODE == 0) ? blockIdx.z : 0;
    const float* A = args.A[z];
    const float* W = args.W[z];
    const float* bias = args.bias[z];
    float* out     = args.out[z];
    const float scale = args.scale[z];

    const int tid  = threadIdx.x;
    const int warp = tid >> 5;
    const int wm   = warp & 3;
    const int wn   = warp >> 2;
    const int row0 = blockIdx.y * 128;
    const int col0 = blockIdx.x * 128;

    const int lr  = tid >> 3;
    const int lc4 = (tid & 7) * 4;

    wmma::fragment<wmma::accumulator, 16, 16, 8, float> acc[2][4];
    #pragma unroll
    for (int mi = 0; mi < 2; mi++)
        #pragma unroll
        for (int ni = 0; ni < 4; ni++)
            wmma::fill_fragment(acc[mi][ni], 0.0f);

    auto stage = [&](int kt, int st) {
        float* As = smem + st * 2 * GTILE;
        float* Bs = As + GTILE;
        const int k0 = kt * 32;
        #pragma unroll
        for (int i = 0; i < 4; i++) {
            int r = lr + i * 32;
            cp16(&As[r * GSTRIDE + lc4], &A[(size_t)(row0 + r) * 1024 + k0 + lc4]);
            cp16(&Bs[r * GSTRIDE + lc4], &W[(size_t)(col0 + r) * 1024 + k0 + lc4]);
        }
        cp_commit();
    };

    stage(0, 0);
    const int NT = 1024 / 32;
    for (int t = 0; t < NT; t++) {
        if (t + 1 < NT) { stage(t + 1, (t + 1) & 1); cp_wait<1>(); }
        else            { cp_wait<0>(); }
        __syncthreads();

        float* As = smem + (t & 1) * 2 * GTILE;
        float* Bs = As + GTILE;
        #pragma unroll
        for (int ks = 0; ks < 4; ks++) {
            wmma::fragment<wmma::matrix_a, 16, 16, 8, wmma::precision::tf32, wmma::row_major> a[2];
            wmma::fragment<wmma::matrix_b, 16, 16, 8, wmma::precision::tf32, wmma::col_major> b[4];
            #pragma unroll
            for (int mi = 0; mi < 2; mi++)
                wmma::load_matrix_sync(a[mi], &As[(wm * 32 + mi * 16) * GSTRIDE + ks * 8], GSTRIDE);
            #pragma unroll
            for (int ni = 0; ni < 4; ni++)
                wmma::load_matrix_sync(b[ni], &Bs[(wn * 64 + ni * 16) * GSTRIDE + ks * 8], GSTRIDE);
            #pragma unroll
            for (int mi = 0; mi < 2; mi++)
                #pragma unroll
                for (int ni = 0; ni < 4; ni++)
                    wmma::mma_sync(acc[mi][ni], a[mi], b[ni], acc[mi][ni]);
        }
        __syncthreads();
    }

    float* Cs = smem;
    #pragma unroll
    for (int mi = 0; mi < 2; mi++)
        #pragma unroll
        for (int ni = 0; ni < 4; ni++)
            wmma::store_matrix_sync(&Cs[(wm * 32 + mi * 16) * 132 + wn * 64 + ni * 16],
                                    acc[mi][ni], 132, wmma::mem_row_major);
    __syncthreads();

    for (int idx = tid; idx < 128 * 128; idx += 256) {
        int r = idx >> 7, c = idx & 127;
        int o = col0 + c;
        float v = (Cs[r * 132 + c] + bias[o]) * scale;
        int grow = row0 + r;
        if (MODE == 0) {
            v = f2tff(v);
            int t = grow >> 1, b = grow & 1;
            int h = o >> 6, d = o & 63;
            out[(((size_t)(b * H_DIM + h)) * T_DIM + t) * D_DIM + d] = v;
        } else {
            out[(size_t)grow * E_DIM + o] = v;
        }
    }
}

// ---------------------------------------------------------------------------
// Flash attention v3: 128 threads, 4 warps x 32 queries = 128 q/block,
// 32-key tiles x 64 iters, cp.async double-buffered K/V, register Q/O/state.
// ---------------------------------------------------------------------------
#define AK_PAD 68
#define AV_PAD 72
#define AP_PAD 36

__global__ __launch_bounds__(128)
void attn_kernel(const float* __restrict__ q, const float* __restrict__ k,
                 const float* __restrict__ v, const float* __restrict__ biasg,
                 float* __restrict__ out)
{
    extern __shared__ float sm[];
    float* Kst = sm;                            // 2 x 32 x AK_PAD
    float* Vst = Kst + 2 * 32 * AK_PAD;         // 2 x 32 x AV_PAD
    float* Ps  = Vst + 2 * 32 * AV_PAD;         // 4 warps x 32 x AP_PAD

    const int tid  = threadIdx.x;
    const int warp = tid >> 5;
    const int lane = tid & 31;
    const int g    = lane >> 2;
    const int tig  = lane & 3;
    const int qt0  = blockIdx.x * 128;
    const int bh   = blockIdx.y;
    const int b    = bh >> 4;
    const int h    = bh & 15;

    const float* qb = q + (size_t)bh * T_DIM * D_DIM;
    const float* kb = k + (size_t)bh * T_DIM * D_DIM;
    const float* vb = v + (size_t)bh * T_DIM * D_DIM;
    const float* bg = biasg + (size_t)b * T_DIM;
    float* Pw = Ps + warp * 32 * AP_PAD;

    // Q A-fragments straight from gmem (once per block)
    unsigned qa[8][2][4];
    {
        const float* qw = qb + (size_t)(qt0 + warp * 32) * 64;
        #pragma unroll
        for (int kc = 0; kc < 8; kc++)
            #pragma unroll
            for (int m = 0; m < 2; m++) {
                int r0 = m * 16 + g, r1 = r0 + 8;
                qa[kc][m][0] = __float_as_uint(qw[r0 * 64 + kc * 8 + tig]);
                qa[kc][m][1] = __float_as_uint(qw[r1 * 64 + kc * 8 + tig]);
                qa[kc][m][2] = __float_as_uint(qw[r0 * 64 + kc * 8 + tig + 4]);
                qa[kc][m][3] = __float_as_uint(qw[r1 * 64 + kc * 8 + tig + 4]);
            }
    }

    float o[8][2][4];
    #pragma unroll
    for (int dj = 0; dj < 8; dj++)
        #pragma unroll
        for (int m = 0; m < 2; m++)
            o[dj][m][0] = o[dj][m][1] = o[dj][m][2] = o[dj][m][3] = 0.0f;
    float mr[4] = {-1e30f, -1e30f, -1e30f, -1e30f};
    float lr[4] = {0.0f, 0.0f, 0.0f, 0.0f};

    auto stageKV = [&](int it, int buf) {
        const int s0 = it * 32;
        float* Kd = Kst + buf * 32 * AK_PAD;
        float* Vd = Vst + buf * 32 * AV_PAD;
        #pragma unroll
        for (int i = 0; i < 4; i++) {
            int idx = tid + i * 128;          // 0..511
            int r = idx >> 4, c4 = (idx & 15) * 4;
            cp16(&Kd[r * AK_PAD + c4], &kb[(size_t)(s0 + r) * 64 + c4]);
            cp16(&Vd[r * AV_PAD + c4], &vb[(size_t)(s0 + r) * 64 + c4]);
        }
        cp_commit();
    };

    stageKV(0, 0);
    for (int it = 0; it < 64; it++) {
        cp_wait<0>();
        __syncthreads();
        if (it + 1 < 64) stageKV(it + 1, (it + 1) & 1);

        const float* Ks = Kst + (it & 1) * 32 * AK_PAD;
        const float* Vs = Vst + (it & 1) * 32 * AV_PAD;

        float bsv[4][2];
        #pragma unroll
        for (int j = 0; j < 4; j++) {
            bsv[j][0] = bg[it * 32 + j * 8 + 2 * tig];
            bsv[j][1] = bg[it * 32 + j * 8 + 2 * tig + 1];
        }

        // S = Q @ K^T (128q x 32k per block; per warp 32q x 32k)
        float s[4][2][4];
        #pragma unroll
        for (int j = 0; j < 4; j++)
            #pragma unroll
            for (int m = 0; m < 2; m++)
                s[j][m][0] = s[j][m][1] = s[j][m][2] = s[j][m][3] = 0.0f;
        #pragma unroll
        for (int kc = 0; kc < 8; kc++)
            #pragma unroll
            for (int j = 0; j < 4; j++) {
                unsigned b0 = __float_as_uint(Ks[(j * 8 + g) * AK_PAD + kc * 8 + tig]);
                unsigned b1 = __float_as_uint(Ks[(j * 8 + g) * AK_PAD + kc * 8 + tig + 4]);
                #pragma unroll
                for (int m = 0; m < 2; m++) mma8(s[j][m], qa[kc][m], b0, b1);
            }

        // Online softmax; 4 row states per thread: idx = m*2 + (0:row g, 1:row g+8)
        float vmax[4] = {-1e30f, -1e30f, -1e30f, -1e30f};
        #pragma unroll
        for (int j = 0; j < 4; j++)
            #pragma unroll
            for (int m = 0; m < 2; m++) {
                s[j][m][0] += bsv[j][0]; s[j][m][1] += bsv[j][1];
                s[j][m][2] += bsv[j][0]; s[j][m][3] += bsv[j][1];
                vmax[m * 2]     = fmaxf(vmax[m * 2],     fmaxf(s[j][m][0], s[j][m][1]));
                vmax[m * 2 + 1] = fmaxf(vmax[m * 2 + 1], fmaxf(s[j][m][2], s[j][m][3]));
            }
        float al[4], sum[4];
        #pragma unroll
        for (int st = 0; st < 4; st++) {
            vmax[st] = fmaxf(vmax[st], __shfl_xor_sync(0xffffffffu, vmax[st], 1));
            vmax[st] = fmaxf(vmax[st], __shfl_xor_sync(0xffffffffu, vmax[st], 2));
            float mn = fmaxf(mr[st], vmax[st]);
            al[st] = __expf(mr[st] - mn);
            mr[st] = mn;
            sum[st] = 0.0f;
        }
        #pragma unroll
        for (int j = 0; j < 4; j++)
            #pragma unroll
            for (int m = 0; m < 2; m++) {
                s[j][m][0] = __expf(s[j][m][0] - mr[m * 2]);     sum[m * 2]     += s[j][m][0];
                s[j][m][1] = __expf(s[j][m][1] - mr[m * 2]);     sum[m * 2]     += s[j][m][1];
                s[j][m][2] = __expf(s[j][m][2] - mr[m * 2 + 1]); sum[m * 2 + 1] += s[j][m][2];
                s[j][m][3] = __expf(s[j][m][3] - mr[m * 2 + 1]); sum[m * 2 + 1] += s[j][m][3];
            }
        #pragma unroll
        for (int st = 0; st < 4; st++) {
            sum[st] += __shfl_xor_sync(0xffffffffu, sum[st], 1);
            sum[st] += __shfl_xor_sync(0xffffffffu, sum[st], 2);
            lr[st] = lr[st] * al[st] + sum[st];
        }
        #pragma unroll
        for (int dj = 0; dj < 8; dj++)
            #pragma unroll
            for (int m = 0; m < 2; m++) {
                o[dj][m][0] *= al[m * 2];     o[dj][m][1] *= al[m * 2];
                o[dj][m][2] *= al[m * 2 + 1]; o[dj][m][3] *= al[m * 2 + 1];
            }

        // P acc -> A layout via per-warp smem (tf32-rounded)
        #pragma unroll
        for (int j = 0; j < 4; j++)
            #pragma unroll
            for (int m = 0; m < 2; m++) {
                *(float2*)&Pw[(m * 16 + g) * AP_PAD + j * 8 + 2 * tig] =
                    make_float2(f2tff(s[j][m][0]), f2tff(s[j][m][1]));
                *(float2*)&Pw[(m * 16 + g + 8) * AP_PAD + j * 8 + 2 * tig] =
                    make_float2(f2tff(s[j][m][2]), f2tff(s[j][m][3]));
            }
        __syncwarp();

        // O += P @ V
        #pragma unroll
        for (int kc = 0; kc < 4; kc++) {
            unsigned pa[2][4];
            #pragma unroll
            for (int m = 0; m < 2; m++) {
                pa[m][0] = __float_as_uint(Pw[(m * 16 + g) * AP_PAD + kc * 8 + tig]);
                pa[m][1] = __float_as_uint(Pw[(m * 16 + g + 8) * AP_PAD + kc * 8 + tig]);
                pa[m][2] = __float_as_uint(Pw[(m * 16 + g) * AP_PAD + kc * 8 + tig + 4]);
                pa[m][3] = __float_as_uint(Pw[(m * 16 + g + 8) * AP_PAD + kc * 8 + tig + 4]);
            }
            #pragma unroll
            for (int dj = 0; dj < 8; dj++) {
                unsigned b0 = __float_as_uint(Vs[(kc * 8 + tig) * AV_PAD + dj * 8 + g]);
                unsigned b1 = __float_as_uint(Vs[(kc * 8 + tig + 4) * AV_PAD + dj * 8 + g]);
                #pragma unroll
                for (int m = 0; m < 2; m++) mma8(o[dj][m], pa[m], b0, b1);
            }
        }
        __syncwarp();
    }

    // Epilogue
    #pragma unroll
    for (int m = 0; m < 2; m++) {
        float i0 = (lr[m * 2] > 0.0f)     ? 1.0f / lr[m * 2]     : 0.0f;
        float i1 = (lr[m * 2 + 1] > 0.0f) ? 1.0f / lr[m * 2 + 1] : 0.0f;
        int t0 = qt0 + warp * 32 + m * 16 + g;
        int t1 = t0 + 8;
        float* d0 = out + ((size_t)t0 * B_DIM + b) * E_DIM + h * 64;
        float* d1 = out + ((size_t)t1 * B_DIM + b) * E_DIM + h * 64;
        #pragma unroll
        for (int dj = 0; dj < 8; dj++) {
            *(float2*)&d0[dj * 8 + 2 * tig] =
                make_float2(f2tff(o[dj][m][0] * i0), f2tff(o[dj][m][1] * i0));
            *(float2*)&d1[dj * 8 + 2 * tig] =
                make_float2(f2tff(o[dj][m][2] * i1), f2tff(o[dj][m][3] * i1));
        }
    }
}

// ---------------------------------------------------------------------------
extern "C" void kernel_launch(void* const* d_in, const int* in_sizes, int n_in,
                              void* d_out, int out_size)
{
    (void)in_sizes; (void)n_in; (void)out_size;
    const float* query = (const float*)d_in[0];
    const float* key   = (const float*)d_in[1];
    const float* value = (const float*)d_in[2];
    const unsigned char* mask = (const unsigned char*)d_in[3];
    const float* wq = (const float*)d_in[4];
    const float* bq = (const float*)d_in[5];
    const float* wk = (const float*)d_in[6];
    const float* bk = (const float*)d_in[7];
    const float* wv = (const float*)d_in[8];
    const float* bv = (const float*)d_in[9];
    const float* wo = (const float*)d_in[10];
    const float* bo = (const float*)d_in[11];
    float* out = (float*)d_out;

    float *qb, *kb, *vb, *ab, *bb, *inr, *wr;
    cudaGetSymbolAddress((void**)&qb, g_q);
    cudaGetSymbolAddress((void**)&kb, g_k);
    cudaGetSymbolAddress((void**)&vb, g_v);
    cudaGetSymbolAddress((void**)&ab, g_attn);
    cudaGetSymbolAddress((void**)&bb, g_bias);
    cudaGetSymbolAddress((void**)&inr, g_in_r);
    cudaGetSymbolAddress((void**)&wr, g_w_r);

    const int IN  = M_DIM * E_DIM;
    const int WSZ = E_DIM * E_DIM;

    static int smem_set = 0;
    const int gemm_smem = 2 * 2 * GTILE * (int)sizeof(float);
    const int attn_smem = (2 * 32 * AK_PAD + 2 * 32 * AV_PAD + 4 * 32 * AP_PAD) * (int)sizeof(float);
    if (!smem_set) {
        cudaFuncSetAttribute(gemm_kernel<0>, cudaFuncAttributeMaxDynamicSharedMemorySize, gemm_smem);
        cudaFuncSetAttribute(gemm_kernel<1>, cudaFuncAttributeMaxDynamicSharedMemorySize, gemm_smem);
        cudaFuncSetAttribute(attn_kernel, cudaFuncAttributeMaxDynamicSharedMemorySize, attn_smem);
        smem_set = 1;
    }

    preround_kernel<<<(3 * IN + 4 * WSZ) / 4 / 256, 256>>>(
        (const float4*)query, (const float4*)key, (const float4*)value,
        (const float4*)wq, (const float4*)wk, (const float4*)wv, (const float4*)wo,
        (float4*)inr, (float4*)wr);

    mask_bias_kernel<<<(B_DIM * T_DIM + 255) / 256, 256>>>(mask, bb);

    GemmArgs qkv;
    qkv.A[0] = inr;           qkv.A[1] = inr + IN;      qkv.A[2] = inr + 2 * IN;
    qkv.W[0] = wr;            qkv.W[1] = wr + WSZ;      qkv.W[2] = wr + 2 * WSZ;
    qkv.bias[0] = bq;         qkv.bias[1] = bk;         qkv.bias[2] = bv;
    qkv.out[0] = qb;          qkv.out[1] = kb;          qkv.out[2] = vb;
    qkv.scale[0] = 0.125f;    qkv.scale[1] = 1.0f;      qkv.scale[2] = 1.0f;

    dim3 gqkv(E_DIM / 128, M_DIM / 128, 3);
    gemm_kernel<0><<<gqkv, 256, gemm_smem>>>(qkv);

    dim3 gattn(T_DIM / 128, B_DIM * H_DIM);   // (16, 32)
    attn_kernel<<<gattn, 128, attn_smem>>>(qb, kb, vb, bb, ab);

    GemmArgs oargs;
    oargs.A[0] = ab;   oargs.W[0] = wr + 3 * WSZ;  oargs.bias[0] = bo;
    oargs.out[0] = out; oargs.scale[0] = 1.0f;
    oargs.A[1] = oargs.A[2] = ab; oargs.W[1] = oargs.W[2] = wr;
    oargs.bias[1] = oargs.bias[2] = bo; oargs.out[1] = oargs.out[2] = out;
    oargs.scale[1] = oargs.scale[2] = 1.0f;

    dim3 gop(E_DIM / 128, M_DIM / 128, 1);
    gemm_kernel<1><<<gop, 256, gemm_smem>>>(oargs);
}

// round 5
// speedup vs baseline: 2.3669x; 1.2274x over previous
#include <cuda_runtime.h>

#define T_DIM 2048
#define B_DIM 2
#define E_DIM 1024
#define H_DIM 16
#define D_DIM 64
#define M_DIM (T_DIM * B_DIM)

__device__ float g_q[B_DIM * H_DIM * T_DIM * D_DIM];
__device__ float g_k[B_DIM * H_DIM * T_DIM * D_DIM];
__device__ float g_v[B_DIM * H_DIM * T_DIM * D_DIM];
__device__ float g_attn[T_DIM * B_DIM * E_DIM];
__device__ float g_bias[B_DIM * T_DIM];
__device__ float g_in_r[3 * M_DIM * E_DIM];
__device__ float g_w_r[4 * E_DIM * E_DIM];

__device__ __forceinline__ unsigned f2tf(float x) {
    unsigned u;
    asm("cvt.rna.tf32.f32 %0, %1;" : "=r"(u) : "f"(x));
    return u;
}
__device__ __forceinline__ float f2tff(float x) { return __uint_as_float(f2tf(x)); }

__device__ __forceinline__ void cp16(float* smem, const float* gmem) {
    unsigned s = (unsigned)__cvta_generic_to_shared(smem);
    asm volatile("cp.async.cg.shared.global [%0], [%1], 16;\n" :: "r"(s), "l"(gmem));
}
__device__ __forceinline__ void cp_commit() { asm volatile("cp.async.commit_group;\n"); }
template <int N> __device__ __forceinline__ void cp_wait() {
    asm volatile("cp.async.wait_group %0;\n" :: "n"(N));
}

__device__ __forceinline__ void mma8(float* d, const unsigned* a, unsigned b0, unsigned b1) {
    asm volatile(
        "mma.sync.aligned.m16n8k8.row.col.f32.tf32.tf32.f32 "
        "{%0,%1,%2,%3},{%4,%5,%6,%7},{%8,%9},{%0,%1,%2,%3};"
        : "+f"(d[0]), "+f"(d[1]), "+f"(d[2]), "+f"(d[3])
        : "r"(a[0]), "r"(a[1]), "r"(a[2]), "r"(a[3]), "r"(b0), "r"(b1));
}

// ---------------------------------------------------------------------------
__global__ void preround_kernel(const float4* __restrict__ q, const float4* __restrict__ k,
                                const float4* __restrict__ v, const float4* __restrict__ wq,
                                const float4* __restrict__ wk, const float4* __restrict__ wv,
                                const float4* __restrict__ wo, float4* __restrict__ din,
                                float4* __restrict__ dw)
{
    const int IN4 = M_DIM * E_DIM / 4;
    const int W4  = E_DIM * E_DIM / 4;
    int i = blockIdx.x * blockDim.x + threadIdx.x;
    const float4* s;
    float4* d;
    if (i < 3 * IN4) {
        s = (i < IN4) ? q + i : (i < 2 * IN4 ? k + (i - IN4) : v + (i - 2 * IN4));
        d = din + i;
    } else {
        int j = i - 3 * IN4;
        s = (j < W4) ? wq + j : j < 2 * W4 ? wk + (j - W4) : j < 3 * W4 ? wv + (j - 2 * W4)
                                                                        : wo + (j - 3 * W4);
        d = dw + j;
    }
    float4 x = *s;
    x.x = f2tff(x.x); x.y = f2tff(x.y); x.z = f2tff(x.z); x.w = f2tff(x.w);
    *d = x;
}

__global__ void mask_bias_kernel(const unsigned char* __restrict__ mask, float* __restrict__ bias) {
    int i = blockIdx.x * blockDim.x + threadIdx.x;
    if (i < B_DIM * T_DIM) bias[i] = mask[i] ? -1e30f : 0.0f;
}

// ---------------------------------------------------------------------------
// GEMM v2: raw mma m16n8k8, 128x128 block, 64x64 warp tile (4 warps),
// BK=16, 3-stage cp.async, register epilogue (no smem round-trip).
// ---------------------------------------------------------------------------
struct GemmArgs {
    const float* A[3];
    const float* W[3];
    const float* bias[3];
    float* out[3];
    float scale[3];
};

#define GPAD   20
#define GSTAGE (128 * GPAD)   // floats per A (or B) tile per stage

template <int MODE>
__global__ __launch_bounds__(128, 2)
void gemm_kernel(GemmArgs args)
{
    extern __shared__ float smem[];   // 3 stages * 2 * GSTAGE floats = 61440 B

    const int z    = (MODE == 0) ? blockIdx.z : 0;
    const float* A = args.A[z];
    const float* W = args.W[z];
    const float* bias = args.bias[z];
    float* out     = args.out[z];
    const float scale = args.scale[z];

    const int tid  = threadIdx.x;
    const int warp = tid >> 5;
    const int lane = tid & 31;
    const int g    = lane >> 2;
    const int tig  = lane & 3;
    const int wm   = warp >> 1;          // 2 warps along M (64 rows each)
    const int wn   = warp & 1;           // 2 warps along N (64 cols each)
    const int row0 = blockIdx.y * 128;
    const int col0 = blockIdx.x * 128;

    float acc[4][8][4];
    #pragma unroll
    for (int mi = 0; mi < 4; mi++)
        #pragma unroll
        for (int ni = 0; ni < 8; ni++)
            acc[mi][ni][0] = acc[mi][ni][1] = acc[mi][ni][2] = acc[mi][ni][3] = 0.0f;

    const float* Agb = &A[(size_t)(row0 + tid) * 1024];
    const float* Wgb = &W[(size_t)(col0 + tid) * 1024];

    auto stage = [&](int kt, int st) {
        float* Ad = smem + st * 2 * GSTAGE + tid * GPAD;
        float* Bd = Ad + GSTAGE;
        const int k0 = kt * 16;
        #pragma unroll
        for (int c = 0; c < 16; c += 4) {
            cp16(Ad + c, Agb + k0 + c);
            cp16(Bd + c, Wgb + k0 + c);
        }
        cp_commit();
    };

    auto compute = [&](int st) {
        const float* As = smem + st * 2 * GSTAGE;
        const float* Bs = As + GSTAGE;
        #pragma unroll
        for (int kc = 0; kc < 2; kc++) {
            unsigned af[4][4];
            unsigned bf[8][2];
            #pragma unroll
            for (int mi = 0; mi < 4; mi++) {
                const float* ap = &As[(wm * 64 + mi * 16) * GPAD + kc * 8];
                af[mi][0] = __float_as_uint(ap[g * GPAD + tig]);
                af[mi][1] = __float_as_uint(ap[(g + 8) * GPAD + tig]);
                af[mi][2] = __float_as_uint(ap[g * GPAD + tig + 4]);
                af[mi][3] = __float_as_uint(ap[(g + 8) * GPAD + tig + 4]);
            }
            #pragma unroll
            for (int ni = 0; ni < 8; ni++) {
                const float* bp = &Bs[(wn * 64 + ni * 8 + g) * GPAD + kc * 8];
                bf[ni][0] = __float_as_uint(bp[tig]);
                bf[ni][1] = __float_as_uint(bp[tig + 4]);
            }
            #pragma unroll
            for (int mi = 0; mi < 4; mi++)
                #pragma unroll
                for (int ni = 0; ni < 8; ni++)
                    mma8(acc[mi][ni], af[mi], bf[ni][0], bf[ni][1]);
        }
    };

    const int NT = 1024 / 16;   // 64
    stage(0, 0);
    stage(1, 1);
    for (int t = 0; t < NT; t++) {
        if (t + 1 < NT) cp_wait<1>();
        else            cp_wait<0>();
        __syncthreads();
        if (t + 2 < NT) stage(t + 2, (t + 2) % 3);
        compute(t % 3);
    }

    // Register epilogue
    float bvals[8][2];
    #pragma unroll
    for (int ni = 0; ni < 8; ni++) {
        int c = col0 + wn * 64 + ni * 8 + 2 * tig;
        bvals[ni][0] = __ldg(&bias[c]);
        bvals[ni][1] = __ldg(&bias[c + 1]);
    }
    #pragma unroll
    for (int mi = 0; mi < 4; mi++) {
        #pragma unroll
        for (int rr = 0; rr < 2; rr++) {
            int r = row0 + wm * 64 + mi * 16 + g + rr * 8;   // = t*B + b
            #pragma unroll
            for (int ni = 0; ni < 8; ni++) {
                int o = col0 + wn * 64 + ni * 8 + 2 * tig;
                float v0 = (acc[mi][ni][rr * 2]     + bvals[ni][0]) * scale;
                float v1 = (acc[mi][ni][rr * 2 + 1] + bvals[ni][1]) * scale;
                if (MODE == 0) {
                    v0 = f2tff(v0); v1 = f2tff(v1);
                    int t = r >> 1, b = r & 1;
                    int h = o >> 6, d = o & 63;
                    *(float2*)&out[(((size_t)(b * H_DIM + h)) * T_DIM + t) * D_DIM + d] =
                        make_float2(v0, v1);
                } else {
                    *(float2*)&out[(size_t)r * E_DIM + o] = make_float2(v0, v1);
                }
            }
        }
    }
}

// ---------------------------------------------------------------------------
// Flash attention v4: 256 threads (8 warps x 32 queries = 256 q/block),
// 64-key tiles x 32 iters, cp.async double-buffered K/V, register Q/O/state.
// ---------------------------------------------------------------------------
#define AK_PAD 68
#define AV_PAD 72
#define AP_PAD 68

__global__ __launch_bounds__(256)
void attn_kernel(const float* __restrict__ q, const float* __restrict__ k,
                 const float* __restrict__ v, const float* __restrict__ biasg,
                 float* __restrict__ out)
{
    extern __shared__ float sm[];
    float* Kst = sm;                            // 2 x 64 x AK_PAD
    float* Vst = Kst + 2 * 64 * AK_PAD;         // 2 x 64 x AV_PAD
    float* Ps  = Vst + 2 * 64 * AV_PAD;         // 8 warps x 32 x AP_PAD

    const int tid  = threadIdx.x;
    const int warp = tid >> 5;
    const int lane = tid & 31;
    const int g    = lane >> 2;
    const int tig  = lane & 3;
    const int qt0  = blockIdx.x * 256;
    const int bh   = blockIdx.y;
    const int b    = bh >> 4;
    const int h    = bh & 15;

    const float* qb = q + (size_t)bh * T_DIM * D_DIM;
    const float* kb = k + (size_t)bh * T_DIM * D_DIM;
    const float* vb = v + (size_t)bh * T_DIM * D_DIM;
    const float* bg = biasg + (size_t)b * T_DIM;
    float* Pw = Ps + warp * 32 * AP_PAD;

    // Q A-fragments straight from gmem (once per block)
    unsigned qa[8][2][4];
    {
        const float* qw = qb + (size_t)(qt0 + warp * 32) * 64;
        #pragma unroll
        for (int kc = 0; kc < 8; kc++)
            #pragma unroll
            for (int m = 0; m < 2; m++) {
                int r0 = m * 16 + g, r1 = r0 + 8;
                qa[kc][m][0] = __float_as_uint(qw[r0 * 64 + kc * 8 + tig]);
                qa[kc][m][1] = __float_as_uint(qw[r1 * 64 + kc * 8 + tig]);
                qa[kc][m][2] = __float_as_uint(qw[r0 * 64 + kc * 8 + tig + 4]);
                qa[kc][m][3] = __float_as_uint(qw[r1 * 64 + kc * 8 + tig + 4]);
            }
    }

    float o[8][2][4];
    #pragma unroll
    for (int dj = 0; dj < 8; dj++)
        #pragma unroll
        for (int m = 0; m < 2; m++)
            o[dj][m][0] = o[dj][m][1] = o[dj][m][2] = o[dj][m][3] = 0.0f;
    float mr[4] = {-1e30f, -1e30f, -1e30f, -1e30f};
    float lr[4] = {0.0f, 0.0f, 0.0f, 0.0f};

    auto stageKV = [&](int it, int buf) {
        const int s0 = it * 64;
        float* Kd = Kst + buf * 64 * AK_PAD;
        float* Vd = Vst + buf * 64 * AV_PAD;
        #pragma unroll
        for (int i = 0; i < 4; i++) {
            int idx = tid + i * 256;          // 0..1023
            int r = idx >> 4, c4 = (idx & 15) * 4;
            cp16(&Kd[r * AK_PAD + c4], &kb[(size_t)(s0 + r) * 64 + c4]);
            cp16(&Vd[r * AV_PAD + c4], &vb[(size_t)(s0 + r) * 64 + c4]);
        }
        cp_commit();
    };

    stageKV(0, 0);
    for (int it = 0; it < 32; it++) {
        cp_wait<0>();
        __syncthreads();
        if (it + 1 < 32) stageKV(it + 1, (it + 1) & 1);

        const float* Ks = Kst + (it & 1) * 64 * AK_PAD;
        const float* Vs = Vst + (it & 1) * 64 * AV_PAD;

        // S = Q @ K^T (per warp 32q x 64k)
        float s[8][2][4];
        #pragma unroll
        for (int j = 0; j < 8; j++)
            #pragma unroll
            for (int m = 0; m < 2; m++)
                s[j][m][0] = s[j][m][1] = s[j][m][2] = s[j][m][3] = 0.0f;
        #pragma unroll
        for (int kc = 0; kc < 8; kc++)
            #pragma unroll
            for (int j = 0; j < 8; j++) {
                unsigned b0 = __float_as_uint(Ks[(j * 8 + g) * AK_PAD + kc * 8 + tig]);
                unsigned b1 = __float_as_uint(Ks[(j * 8 + g) * AK_PAD + kc * 8 + tig + 4]);
                #pragma unroll
                for (int m = 0; m < 2; m++) mma8(s[j][m], qa[kc][m], b0, b1);
            }

        // Online softmax; 4 row states per thread
        float vmax[4] = {-1e30f, -1e30f, -1e30f, -1e30f};
        #pragma unroll
        for (int j = 0; j < 8; j++) {
            float b0v = __ldg(&bg[it * 64 + j * 8 + 2 * tig]);
            float b1v = __ldg(&bg[it * 64 + j * 8 + 2 * tig + 1]);
            #pragma unroll
            for (int m = 0; m < 2; m++) {
                s[j][m][0] += b0v; s[j][m][1] += b1v;
                s[j][m][2] += b0v; s[j][m][3] += b1v;
                vmax[m * 2]     = fmaxf(vmax[m * 2],     fmaxf(s[j][m][0], s[j][m][1]));
                vmax[m * 2 + 1] = fmaxf(vmax[m * 2 + 1], fmaxf(s[j][m][2], s[j][m][3]));
            }
        }
        float al[4], sum[4];
        #pragma unroll
        for (int st = 0; st < 4; st++) {
            vmax[st] = fmaxf(vmax[st], __shfl_xor_sync(0xffffffffu, vmax[st], 1));
            vmax[st] = fmaxf(vmax[st], __shfl_xor_sync(0xffffffffu, vmax[st], 2));
            float mn = fmaxf(mr[st], vmax[st]);
            al[st] = __expf(mr[st] - mn);
            mr[st] = mn;
            sum[st] = 0.0f;
        }
        #pragma unroll
        for (int j = 0; j < 8; j++)
            #pragma unroll
            for (int m = 0; m < 2; m++) {
                s[j][m][0] = __expf(s[j][m][0] - mr[m * 2]);     sum[m * 2]     += s[j][m][0];
                s[j][m][1] = __expf(s[j][m][1] - mr[m * 2]);     sum[m * 2]     += s[j][m][1];
                s[j][m][2] = __expf(s[j][m][2] - mr[m * 2 + 1]); sum[m * 2 + 1] += s[j][m][2];
                s[j][m][3] = __expf(s[j][m][3] - mr[m * 2 + 1]); sum[m * 2 + 1] += s[j][m][3];
            }
        #pragma unroll
        for (int st = 0; st < 4; st++) {
            sum[st] += __shfl_xor_sync(0xffffffffu, sum[st], 1);
            sum[st] += __shfl_xor_sync(0xffffffffu, sum[st], 2);
            lr[st] = lr[st] * al[st] + sum[st];
        }
        #pragma unroll
        for (int dj = 0; dj < 8; dj++)
            #pragma unroll
            for (int m = 0; m < 2; m++) {
                o[dj][m][0] *= al[m * 2];     o[dj][m][1] *= al[m * 2];
                o[dj][m][2] *= al[m * 2 + 1]; o[dj][m][3] *= al[m * 2 + 1];
            }

        // P acc -> A layout via per-warp smem (tf32-rounded)
        #pragma unroll
        for (int j = 0; j < 8; j++)
            #pragma unroll
            for (int m = 0; m < 2; m++) {
                *(float2*)&Pw[(m * 16 + g) * AP_PAD + j * 8 + 2 * tig] =
                    make_float2(f2tff(s[j][m][0]), f2tff(s[j][m][1]));
                *(float2*)&Pw[(m * 16 + g + 8) * AP_PAD + j * 8 + 2 * tig] =
                    make_float2(f2tff(s[j][m][2]), f2tff(s[j][m][3]));
            }
        __syncwarp();

        // O += P @ V
        #pragma unroll
        for (int kc = 0; kc < 8; kc++) {
            unsigned pa[2][4];
            #pragma unroll
            for (int m = 0; m < 2; m++) {
                pa[m][0] = __float_as_uint(Pw[(m * 16 + g) * AP_PAD + kc * 8 + tig]);
                pa[m][1] = __float_as_uint(Pw[(m * 16 + g + 8) * AP_PAD + kc * 8 + tig]);
                pa[m][2] = __float_as_uint(Pw[(m * 16 + g) * AP_PAD + kc * 8 + tig + 4]);
                pa[m][3] = __float_as_uint(Pw[(m * 16 + g + 8) * AP_PAD + kc * 8 + tig + 4]);
            }
            #pragma unroll
            for (int dj = 0; dj < 8; dj++) {
                unsigned b0 = __float_as_uint(Vs[(kc * 8 + tig) * AV_PAD + dj * 8 + g]);
                unsigned b1 = __float_as_uint(Vs[(kc * 8 + tig + 4) * AV_PAD + dj * 8 + g]);
                #pragma unroll
                for (int m = 0; m < 2; m++) mma8(o[dj][m], pa[m], b0, b1);
            }
        }
        __syncwarp();
    }

    // Epilogue
    #pragma unroll
    for (int m = 0; m < 2; m++) {
        float i0 = (lr[m * 2] > 0.0f)     ? 1.0f / lr[m * 2]     : 0.0f;
        float i1 = (lr[m * 2 + 1] > 0.0f) ? 1.0f / lr[m * 2 + 1] : 0.0f;
        int t0 = qt0 + warp * 32 + m * 16 + g;
        int t1 = t0 + 8;
        float* d0 = out + ((size_t)t0 * B_DIM + b) * E_DIM + h * 64;
        float* d1 = out + ((size_t)t1 * B_DIM + b) * E_DIM + h * 64;
        #pragma unroll
        for (int dj = 0; dj < 8; dj++) {
            *(float2*)&d0[dj * 8 + 2 * tig] =
                make_float2(f2tff(o[dj][m][0] * i0), f2tff(o[dj][m][1] * i0));
            *(float2*)&d1[dj * 8 + 2 * tig] =
                make_float2(f2tff(o[dj][m][2] * i1), f2tff(o[dj][m][3] * i1));
        }
    }
}

// ---------------------------------------------------------------------------
extern "C" void kernel_launch(void* const* d_in, const int* in_sizes, int n_in,
                              void* d_out, int out_size)
{
    (void)in_sizes; (void)n_in; (void)out_size;
    const float* query = (const float*)d_in[0];
    const float* key   = (const float*)d_in[1];
    const float* value = (const float*)d_in[2];
    const unsigned char* mask = (const unsigned char*)d_in[3];
    const float* wq = (const float*)d_in[4];
    const float* bq = (const float*)d_in[5];
    const float* wk = (const float*)d_in[6];
    const float* bk = (const float*)d_in[7];
    const float* wv = (const float*)d_in[8];
    const float* bv = (const float*)d_in[9];
    const float* wo = (const float*)d_in[10];
    const float* bo = (const float*)d_in[11];
    float* out = (float*)d_out;

    float *qb, *kb, *vb, *ab, *bb, *inr, *wr;
    cudaGetSymbolAddress((void**)&qb, g_q);
    cudaGetSymbolAddress((void**)&kb, g_k);
    cudaGetSymbolAddress((void**)&vb, g_v);
    cudaGetSymbolAddress((void**)&ab, g_attn);
    cudaGetSymbolAddress((void**)&bb, g_bias);
    cudaGetSymbolAddress((void**)&inr, g_in_r);
    cudaGetSymbolAddress((void**)&wr, g_w_r);

    const int IN  = M_DIM * E_DIM;
    const int WSZ = E_DIM * E_DIM;

    static int smem_set = 0;
    const int gemm_smem = 3 * 2 * GSTAGE * (int)sizeof(float);   // 61440
    const int attn_smem = (2 * 64 * AK_PAD + 2 * 64 * AV_PAD + 8 * 32 * AP_PAD) * (int)sizeof(float);
    if (!smem_set) {
        cudaFuncSetAttribute(gemm_kernel<0>, cudaFuncAttributeMaxDynamicSharedMemorySize, gemm_smem);
        cudaFuncSetAttribute(gemm_kernel<1>, cudaFuncAttributeMaxDynamicSharedMemorySize, gemm_smem);
        cudaFuncSetAttribute(attn_kernel, cudaFuncAttributeMaxDynamicSharedMemorySize, attn_smem);
        smem_set = 1;
    }

    preround_kernel<<<(3 * IN + 4 * WSZ) / 4 / 256, 256>>>(
        (const float4*)query, (const float4*)key, (const float4*)value,
        (const float4*)wq, (const float4*)wk, (const float4*)wv, (const float4*)wo,
        (float4*)inr, (float4*)wr);

    mask_bias_kernel<<<(B_DIM * T_DIM + 255) / 256, 256>>>(mask, bb);

    GemmArgs qkv;
    qkv.A[0] = inr;           qkv.A[1] = inr + IN;      qkv.A[2] = inr + 2 * IN;
    qkv.W[0] = wr;            qkv.W[1] = wr + WSZ;      qkv.W[2] = wr + 2 * WSZ;
    qkv.bias[0] = bq;         qkv.bias[1] = bk;         qkv.bias[2] = bv;
    qkv.out[0] = qb;          qkv.out[1] = kb;          qkv.out[2] = vb;
    qkv.scale[0] = 0.125f;    qkv.scale[1] = 1.0f;      qkv.scale[2] = 1.0f;

    dim3 gqkv(E_DIM / 128, M_DIM / 128, 3);   // (8, 32, 3)
    gemm_kernel<0><<<gqkv, 128, gemm_smem>>>(qkv);

    dim3 gattn(T_DIM / 256, B_DIM * H_DIM);   // (8, 32)
    attn_kernel<<<gattn, 256, attn_smem>>>(qb, kb, vb, bb, ab);

    GemmArgs oargs;
    oargs.A[0] = ab;   oargs.W[0] = wr + 3 * WSZ;  oargs.bias[0] = bo;
    oargs.out[0] = out; oargs.scale[0] = 1.0f;
    oargs.A[1] = oargs.A[2] = ab; oargs.W[1] = oargs.W[2] = wr;
    oargs.bias[1] = oargs.bias[2] = bo; oargs.out[1] = oargs.out[2] = out;
    oargs.scale[1] = oargs.scale[2] = 1.0f;

    dim3 gop(E_DIM / 128, M_DIM / 128, 1);    // (8, 32)
    gemm_kernel<1><<<gop, 128, gemm_smem>>>(oargs);
}

// round 9
// speedup vs baseline: 2.3839x; 1.0072x over previous
#include <cuda_runtime.h>
#include <cstdint>

#define T_DIM 2048
#define B_DIM 2
#define E_DIM 1024
#define H_DIM 16
#define D_DIM 64
#define M_DIM (T_DIM * B_DIM)

__device__ float g_q[B_DIM * H_DIM * T_DIM * D_DIM];
__device__ float g_k[B_DIM * H_DIM * T_DIM * D_DIM];
__device__ float g_v[B_DIM * H_DIM * T_DIM * D_DIM];
__device__ float g_attn[T_DIM * B_DIM * E_DIM];
__device__ float g_bias[B_DIM * T_DIM];
__device__ float g_in_r[3 * M_DIM * E_DIM];
__device__ float g_w_r[4 * E_DIM * E_DIM];

__device__ __forceinline__ unsigned f2tf(float x) {
    unsigned u;
    asm("cvt.rna.tf32.f32 %0, %1;" : "=r"(u) : "f"(x));
    return u;
}
__device__ __forceinline__ float f2tff(float x) { return __uint_as_float(f2tf(x)); }
__device__ __forceinline__ float ex2f(float x) {
    float y;
    asm("ex2.approx.f32 %0, %1;" : "=f"(y) : "f"(x));
    return y;
}

__device__ __forceinline__ void cp16(float* smem, const float* gmem) {
    unsigned s = (unsigned)__cvta_generic_to_shared(smem);
    asm volatile("cp.async.cg.shared.global [%0], [%1], 16;\n" :: "r"(s), "l"(gmem));
}
__device__ __forceinline__ void cp_commit() { asm volatile("cp.async.commit_group;\n"); }
template <int N> __device__ __forceinline__ void cp_wait() {
    asm volatile("cp.async.wait_group %0;\n" :: "n"(N));
}

__device__ __forceinline__ void mma8(float* d, const unsigned* a, unsigned b0, unsigned b1) {
    asm volatile(
        "mma.sync.aligned.m16n8k8.row.col.f32.tf32.tf32.f32 "
        "{%0,%1,%2,%3},{%4,%5,%6,%7},{%8,%9},{%0,%1,%2,%3};"
        : "+f"(d[0]), "+f"(d[1]), "+f"(d[2]), "+f"(d[3])
        : "r"(a[0]), "r"(a[1]), "r"(a[2]), "r"(a[3]), "r"(b0), "r"(b1));
}

// ---------------------------------------------------------------------------
__global__ void preround_kernel(const float4* __restrict__ q, const float4* __restrict__ k,
                                const float4* __restrict__ v, const float4* __restrict__ wq,
                                const float4* __restrict__ wk, const float4* __restrict__ wv,
                                const float4* __restrict__ wo, float4* __restrict__ din,
                                float4* __restrict__ dw)
{
    const int IN4 = M_DIM * E_DIM / 4;
    const int W4  = E_DIM * E_DIM / 4;
    int i = blockIdx.x * blockDim.x + threadIdx.x;
    const float4* s;
    float4* d;
    if (i < 3 * IN4) {
        s = (i < IN4) ? q + i : (i < 2 * IN4 ? k + (i - IN4) : v + (i - 2 * IN4));
        d = din + i;
    } else {
        int j = i - 3 * IN4;
        s = (j < W4) ? wq + j : j < 2 * W4 ? wk + (j - W4) : j < 3 * W4 ? wv + (j - 2 * W4)
                                                                        : wo + (j - 3 * W4);
        d = dw + j;
    }
    float4 x = *s;
    x.x = f2tff(x.x); x.y = f2tff(x.y); x.z = f2tff(x.z); x.w = f2tff(x.w);
    *d = x;
}

// bias pre-scaled by log2e (softmax runs in log2 domain)
__global__ void mask_bias_kernel(const unsigned char* __restrict__ mask, float* __restrict__ bias) {
    int i = blockIdx.x * blockDim.x + threadIdx.x;
    if (i < B_DIM * T_DIM) bias[i] = mask[i] ? -1.4426950e30f : 0.0f;
}

// ---------------------------------------------------------------------------
// GEMM (R5): raw mma m16n8k8, 128x128 block, 64x64 warp tile (4 warps),
// BK=16, 3-stage cp.async, register epilogue.
// ---------------------------------------------------------------------------
struct GemmArgs {
    const float* A[3];
    const float* W[3];
    const float* bias[3];
    float* out[3];
    float scale[3];
};

#define GPAD   20
#define GSTAGE (128 * GPAD)

template <int MODE>
__global__ __launch_bounds__(128, 2)
void gemm_kernel(GemmArgs args)
{
    extern __shared__ float smem[];

    const int z    = (MODE == 0) ? blockIdx.z : 0;
    const float* A = args.A[z];
    const float* W = args.W[z];
    const float* bias = args.bias[z];
    float* out     = args.out[z];
    const float scale = args.scale[z];

    const int tid  = threadIdx.x;
    const int warp = tid >> 5;
    const int lane = tid & 31;
    const int g    = lane >> 2;
    const int tig  = lane & 3;
    const int wm   = warp >> 1;
    const int wn   = warp & 1;
    const int row0 = blockIdx.y * 128;
    const int col0 = blockIdx.x * 128;

    float acc[4][8][4];
    #pragma unroll
    for (int mi = 0; mi < 4; mi++)
        #pragma unroll
        for (int ni = 0; ni < 8; ni++)
            acc[mi][ni][0] = acc[mi][ni][1] = acc[mi][ni][2] = acc[mi][ni][3] = 0.0f;

    const float* Agb = &A[(size_t)(row0 + tid) * 1024];
    const float* Wgb = &W[(size_t)(col0 + tid) * 1024];

    auto stage = [&](int kt, int st) {
        float* Ad = smem + st * 2 * GSTAGE + tid * GPAD;
        float* Bd = Ad + GSTAGE;
        const int k0 = kt * 16;
        #pragma unroll
        for (int c = 0; c < 16; c += 4) {
            cp16(Ad + c, Agb + k0 + c);
            cp16(Bd + c, Wgb + k0 + c);
        }
        cp_commit();
    };

    auto compute = [&](int st) {
        const float* As = smem + st * 2 * GSTAGE;
        const float* Bs = As + GSTAGE;
        #pragma unroll
        for (int kc = 0; kc < 2; kc++) {
            unsigned af[4][4];
            unsigned bf[8][2];
            #pragma unroll
            for (int mi = 0; mi < 4; mi++) {
                const float* ap = &As[(wm * 64 + mi * 16) * GPAD + kc * 8];
                af[mi][0] = __float_as_uint(ap[g * GPAD + tig]);
                af[mi][1] = __float_as_uint(ap[(g + 8) * GPAD + tig]);
                af[mi][2] = __float_as_uint(ap[g * GPAD + tig + 4]);
                af[mi][3] = __float_as_uint(ap[(g + 8) * GPAD + tig + 4]);
            }
            #pragma unroll
            for (int ni = 0; ni < 8; ni++) {
                const float* bp = &Bs[(wn * 64 + ni * 8 + g) * GPAD + kc * 8];
                bf[ni][0] = __float_as_uint(bp[tig]);
                bf[ni][1] = __float_as_uint(bp[tig + 4]);
            }
            #pragma unroll
            for (int mi = 0; mi < 4; mi++)
                #pragma unroll
                for (int ni = 0; ni < 8; ni++)
                    mma8(acc[mi][ni], af[mi], bf[ni][0], bf[ni][1]);
        }
    };

    const int NT = 1024 / 16;
    stage(0, 0);
    stage(1, 1);
    for (int t = 0; t < NT; t++) {
        if (t + 1 < NT) cp_wait<1>();
        else            cp_wait<0>();
        __syncthreads();
        if (t + 2 < NT) stage(t + 2, (t + 2) % 3);
        compute(t % 3);
    }

    float bvals[8][2];
    #pragma unroll
    for (int ni = 0; ni < 8; ni++) {
        int c = col0 + wn * 64 + ni * 8 + 2 * tig;
        bvals[ni][0] = __ldg(&bias[c]);
        bvals[ni][1] = __ldg(&bias[c + 1]);
    }
    #pragma unroll
    for (int mi = 0; mi < 4; mi++) {
        #pragma unroll
        for (int rr = 0; rr < 2; rr++) {
            int r = row0 + wm * 64 + mi * 16 + g + rr * 8;
            #pragma unroll
            for (int ni = 0; ni < 8; ni++) {
                int o = col0 + wn * 64 + ni * 8 + 2 * tig;
                float v0 = (acc[mi][ni][rr * 2]     + bvals[ni][0]) * scale;
                float v1 = (acc[mi][ni][rr * 2 + 1] + bvals[ni][1]) * scale;
                if (MODE == 0) {
                    v0 = f2tff(v0); v1 = f2tff(v1);
                    int t = r >> 1, b = r & 1;
                    int h = o >> 6, d = o & 63;
                    *(float2*)&out[(((size_t)(b * H_DIM + h)) * T_DIM + t) * D_DIM + d] =
                        make_float2(v0, v1);
                } else {
                    *(float2*)&out[(size_t)r * E_DIM + o] = make_float2(v0, v1);
                }
            }
        }
    }
}

// ---------------------------------------------------------------------------
// Flash attention v5b: software-pipelined S(t+1) under softmax(t).
// 256 threads (8 warps x 32 q), 64-key tiles x 32 iters.
// K: 3-buffer cp.async ring (staged early). V: 2-buffer ring (staged after
// softpv consumed it, separate commit group). Q in smem. log2 softmax.
// ---------------------------------------------------------------------------
#define AQ_PAD 68
#define AK_PAD 68
#define AV_PAD 72
#define AP_PAD 68

#define ATTN_SMEM_FLOATS (256 * AQ_PAD + 3 * 64 * AK_PAD + 2 * 64 * AV_PAD + 8 * 32 * AP_PAD)

__global__ __launch_bounds__(256)
void attn_kernel(const float* __restrict__ q, const float* __restrict__ k,
                 const float* __restrict__ v, const float* __restrict__ biasg,
                 float* __restrict__ out)
{
    extern __shared__ float sm[];
    float* Qs  = sm;                                   // 256 x AQ_PAD
    float* Kst = Qs + 256 * AQ_PAD;                    // 3 x 64 x AK_PAD
    float* Vst = Kst + 3 * 64 * AK_PAD;                // 2 x 64 x AV_PAD
    float* Ps  = Vst + 2 * 64 * AV_PAD;                // 8 x 32 x AP_PAD

    const int tid  = threadIdx.x;
    const int warp = tid >> 5;
    const int lane = tid & 31;
    const int g    = lane >> 2;
    const int tig  = lane & 3;
    const int qt0  = blockIdx.x * 256;
    const int bh   = blockIdx.y;
    const int b    = bh >> 4;
    const int h    = bh & 15;

    const float* qb = q + (size_t)bh * T_DIM * D_DIM;
    const float* kb = k + (size_t)bh * T_DIM * D_DIM;
    const float* vb = v + (size_t)bh * T_DIM * D_DIM;
    const float* bg = biasg + (size_t)b * T_DIM;
    float* Pw = Ps + warp * 32 * AP_PAD;

    float o[8][2][4];
    #pragma unroll
    for (int dj = 0; dj < 8; dj++)
        #pragma unroll
        for (int m = 0; m < 2; m++)
            o[dj][m][0] = o[dj][m][1] = o[dj][m][2] = o[dj][m][3] = 0.0f;
    float mr[4] = {-1e30f, -1e30f, -1e30f, -1e30f};
    float lr[4] = {0.0f, 0.0f, 0.0f, 0.0f};
    float sA[8][2][4], sB[8][2][4];

    auto stageK = [&](int it) {            // commits its own group
        float* Kd = Kst + (it % 3) * 64 * AK_PAD;
        const int s0 = it * 64;
        #pragma unroll
        for (int i = 0; i < 4; i++) {
            int idx = tid + i * 256;
            int r = idx >> 4, c4 = (idx & 15) * 4;
            cp16(&Kd[r * AK_PAD + c4], &kb[(size_t)(s0 + r) * 64 + c4]);
        }
        cp_commit();
    };
    auto stageV = [&](int it) {            // commits its own group
        float* Vd = Vst + (it & 1) * 64 * AV_PAD;
        const int s0 = it * 64;
        #pragma unroll
        for (int i = 0; i < 4; i++) {
            int idx = tid + i * 256;
            int r = idx >> 4, c4 = (idx & 15) * 4;
            cp16(&Vd[r * AV_PAD + c4], &vb[(size_t)(s0 + r) * 64 + c4]);
        }
        cp_commit();
    };

    // S = Q @ K^T for tile n into s (Q A-frags from smem)
    auto smma = [&](int n, float (&s)[8][2][4]) {
        const float* Ks = Kst + (n % 3) * 64 * AK_PAD;
        #pragma unroll
        for (int j = 0; j < 8; j++)
            #pragma unroll
            for (int m = 0; m < 2; m++)
                s[j][m][0] = s[j][m][1] = s[j][m][2] = s[j][m][3] = 0.0f;
        #pragma unroll
        for (int kc = 0; kc < 8; kc++) {
            unsigned aq[2][4];
            #pragma unroll
            for (int m = 0; m < 2; m++) {
                const float* qp = Qs + (warp * 32 + m * 16) * AQ_PAD + kc * 8;
                aq[m][0] = __float_as_uint(qp[g * AQ_PAD + tig]);
                aq[m][1] = __float_as_uint(qp[(g + 8) * AQ_PAD + tig]);
                aq[m][2] = __float_as_uint(qp[g * AQ_PAD + tig + 4]);
                aq[m][3] = __float_as_uint(qp[(g + 8) * AQ_PAD + tig + 4]);
            }
            #pragma unroll
            for (int j = 0; j < 8; j++) {
                unsigned b0 = __float_as_uint(Ks[(j * 8 + g) * AK_PAD + kc * 8 + tig]);
                unsigned b1 = __float_as_uint(Ks[(j * 8 + g) * AK_PAD + kc * 8 + tig + 4]);
                #pragma unroll
                for (int m = 0; m < 2; m++) mma8(s[j][m], aq[m], b0, b1);
            }
        }
    };

    // online softmax (log2 domain) + O += P @ V for tile t
    auto softpv = [&](int t, float (&s)[8][2][4]) {
        const float* Vs = Vst + (t & 1) * 64 * AV_PAD;

        float vmax[4] = {-1e30f, -1e30f, -1e30f, -1e30f};
        #pragma unroll
        for (int j = 0; j < 8; j++) {
            float b0v = __ldg(&bg[t * 64 + j * 8 + 2 * tig]);
            float b1v = __ldg(&bg[t * 64 + j * 8 + 2 * tig + 1]);
            #pragma unroll
            for (int m = 0; m < 2; m++) {
                s[j][m][0] += b0v; s[j][m][1] += b1v;
                s[j][m][2] += b0v; s[j][m][3] += b1v;
                vmax[m * 2]     = fmaxf(vmax[m * 2],     fmaxf(s[j][m][0], s[j][m][1]));
                vmax[m * 2 + 1] = fmaxf(vmax[m * 2 + 1], fmaxf(s[j][m][2], s[j][m][3]));
            }
        }
        float al[4], sum[4];
        #pragma unroll
        for (int st = 0; st < 4; st++) {
            vmax[st] = fmaxf(vmax[st], __shfl_xor_sync(0xffffffffu, vmax[st], 1));
            vmax[st] = fmaxf(vmax[st], __shfl_xor_sync(0xffffffffu, vmax[st], 2));
            float mn = fmaxf(mr[st], vmax[st]);
            al[st] = ex2f(mr[st] - mn);
            mr[st] = mn;
            sum[st] = 0.0f;
        }
        #pragma unroll
        for (int j = 0; j < 8; j++)
            #pragma unroll
            for (int m = 0; m < 2; m++) {
                s[j][m][0] = ex2f(s[j][m][0] - mr[m * 2]);     sum[m * 2]     += s[j][m][0];
                s[j][m][1] = ex2f(s[j][m][1] - mr[m * 2]);     sum[m * 2]     += s[j][m][1];
                s[j][m][2] = ex2f(s[j][m][2] - mr[m * 2 + 1]); sum[m * 2 + 1] += s[j][m][2];
                s[j][m][3] = ex2f(s[j][m][3] - mr[m * 2 + 1]); sum[m * 2 + 1] += s[j][m][3];
            }
        #pragma unroll
        for (int st = 0; st < 4; st++) {
            sum[st] += __shfl_xor_sync(0xffffffffu, sum[st], 1);
            sum[st] += __shfl_xor_sync(0xffffffffu, sum[st], 2);
            lr[st] = lr[st] * al[st] + sum[st];
        }
        #pragma unroll
        for (int dj = 0; dj < 8; dj++)
            #pragma unroll
            for (int m = 0; m < 2; m++) {
                o[dj][m][0] *= al[m * 2];     o[dj][m][1] *= al[m * 2];
                o[dj][m][2] *= al[m * 2 + 1]; o[dj][m][3] *= al[m * 2 + 1];
            }

        #pragma unroll
        for (int j = 0; j < 8; j++)
            #pragma unroll
            for (int m = 0; m < 2; m++) {
                *(float2*)&Pw[(m * 16 + g) * AP_PAD + j * 8 + 2 * tig] =
                    make_float2(f2tff(s[j][m][0]), f2tff(s[j][m][1]));
                *(float2*)&Pw[(m * 16 + g + 8) * AP_PAD + j * 8 + 2 * tig] =
                    make_float2(f2tff(s[j][m][2]), f2tff(s[j][m][3]));
            }
        __syncwarp();

        #pragma unroll
        for (int kc = 0; kc < 8; kc++) {
            unsigned pa[2][4];
            #pragma unroll
            for (int m = 0; m < 2; m++) {
                pa[m][0] = __float_as_uint(Pw[(m * 16 + g) * AP_PAD + kc * 8 + tig]);
                pa[m][1] = __float_as_uint(Pw[(m * 16 + g + 8) * AP_PAD + kc * 8 + tig]);
                pa[m][2] = __float_as_uint(Pw[(m * 16 + g) * AP_PAD + kc * 8 + tig + 4]);
                pa[m][3] = __float_as_uint(Pw[(m * 16 + g + 8) * AP_PAD + kc * 8 + tig + 4]);
            }
            #pragma unroll
            for (int dj = 0; dj < 8; dj++) {
                unsigned b0 = __float_as_uint(Vs[(kc * 8 + tig) * AV_PAD + dj * 8 + g]);
                unsigned b1 = __float_as_uint(Vs[(kc * 8 + tig + 4) * AV_PAD + dj * 8 + g]);
                #pragma unroll
                for (int m = 0; m < 2; m++) mma8(o[dj][m], pa[m], b0, b1);
            }
        }
        __syncwarp();
    };

    // Prologue: group A = Q + K(0) + V(0); then K(1); V(1)
    #pragma unroll
    for (int i = 0; i < 16; i++) {
        int idx = tid + i * 256;
        int r = idx >> 4, c4 = (idx & 15) * 4;
        cp16(&Qs[r * AQ_PAD + c4], &qb[(size_t)(qt0 + r) * 64 + c4]);
    }
    {   // K(0) + V(0) share group A with Q
        float* Kd = Kst;
        float* Vd = Vst;
        #pragma unroll
        for (int i = 0; i < 4; i++) {
            int idx = tid + i * 256;
            int r = idx >> 4, c4 = (idx & 15) * 4;
            cp16(&Kd[r * AK_PAD + c4], &kb[(size_t)r * 64 + c4]);
            cp16(&Vd[r * AV_PAD + c4], &vb[(size_t)r * 64 + c4]);
        }
        cp_commit();
    }
    stageK(1);
    stageV(1);
    cp_wait<2>();        // group A done: Q, K0, V0 ready
    __syncthreads();
    smma(0, sA);

    // Pipelined mainloop (2x unrolled, sA/sB alternate)
    for (int t = 0; t < 32; t += 2) {
        // ---- even tile t: consume sA ----
        if (t >= 30) cp_wait<0>(); else cp_wait<1>();   // K(t+1) + V(t) arrived
        __syncthreads();
        if (t + 1 < 32) smma(t + 1, sB);
        if (t + 2 < 32) stageK(t + 2);
        softpv(t, sA);
        __syncthreads();                                // all warps done with V(t)
        if (t + 2 < 32) stageV(t + 2);

        // ---- odd tile u = t+1: consume sB ----
        const int u = t + 1;
        if (u < 32) {
            if (u >= 30) cp_wait<0>(); else cp_wait<1>();
            __syncthreads();
            if (u + 1 < 32) smma(u + 1, sA);
            if (u + 2 < 32) stageK(u + 2);
            softpv(u, sB);
            __syncthreads();
            if (u + 2 < 32) stageV(u + 2);
        }
    }

    // Epilogue
    #pragma unroll
    for (int m = 0; m < 2; m++) {
        float i0 = (lr[m * 2] > 0.0f)     ? 1.0f / lr[m * 2]     : 0.0f;
        float i1 = (lr[m * 2 + 1] > 0.0f) ? 1.0f / lr[m * 2 + 1] : 0.0f;
        int t0 = qt0 + warp * 32 + m * 16 + g;
        int t1 = t0 + 8;
        float* d0 = out + ((size_t)t0 * B_DIM + b) * E_DIM + h * 64;
        float* d1 = out + ((size_t)t1 * B_DIM + b) * E_DIM + h * 64;
        #pragma unroll
        for (int dj = 0; dj < 8; dj++) {
            *(float2*)&d0[dj * 8 + 2 * tig] =
                make_float2(f2tff(o[dj][m][0] * i0), f2tff(o[dj][m][1] * i0));
            *(float2*)&d1[dj * 8 + 2 * tig] =
                make_float2(f2tff(o[dj][m][2] * i1), f2tff(o[dj][m][3] * i1));
        }
    }
}

// ---------------------------------------------------------------------------
extern "C" void kernel_launch(void* const* d_in, const int* in_sizes, int n_in,
                              void* d_out, int out_size)
{
    (void)in_sizes; (void)n_in; (void)out_size;
    const float* query = (const float*)d_in[0];
    const float* key   = (const float*)d_in[1];
    const float* value = (const float*)d_in[2];
    const unsigned char* mask = (const unsigned char*)d_in[3];
    const float* wq = (const float*)d_in[4];
    const float* bq = (const float*)d_in[5];
    const float* wk = (const float*)d_in[6];
    const float* bk = (const float*)d_in[7];
    const float* wv = (const float*)d_in[8];
    const float* bv = (const float*)d_in[9];
    const float* wo = (const float*)d_in[10];
    const float* bo = (const float*)d_in[11];
    float* out = (float*)d_out;

    float *qb, *kb, *vb, *ab, *bb, *inr, *wr;
    cudaGetSymbolAddress((void**)&qb, g_q);
    cudaGetSymbolAddress((void**)&kb, g_k);
    cudaGetSymbolAddress((void**)&vb, g_v);
    cudaGetSymbolAddress((void**)&ab, g_attn);
    cudaGetSymbolAddress((void**)&bb, g_bias);
    cudaGetSymbolAddress((void**)&inr, g_in_r);
    cudaGetSymbolAddress((void**)&wr, g_w_r);

    const int IN  = M_DIM * E_DIM;
    const int WSZ = E_DIM * E_DIM;

    static int smem_set = 0;
    const int gemm_smem = 3 * 2 * GSTAGE * (int)sizeof(float);
    const int attn_smem = ATTN_SMEM_FLOATS * (int)sizeof(float);   // 228352
    if (!smem_set) {
        cudaFuncSetAttribute(gemm_kernel<0>, cudaFuncAttributeMaxDynamicSharedMemorySize, gemm_smem);
        cudaFuncSetAttribute(gemm_kernel<1>, cudaFuncAttributeMaxDynamicSharedMemorySize, gemm_smem);
        cudaFuncSetAttribute(attn_kernel, cudaFuncAttributeMaxDynamicSharedMemorySize, attn_smem);
        smem_set = 1;
    }

    preround_kernel<<<(3 * IN + 4 * WSZ) / 4 / 256, 256>>>(
        (const float4*)query, (const float4*)key, (const float4*)value,
        (const float4*)wq, (const float4*)wk, (const float4*)wv, (const float4*)wo,
        (float4*)inr, (float4*)wr);

    mask_bias_kernel<<<(B_DIM * T_DIM + 255) / 256, 256>>>(mask, bb);

    GemmArgs qkv;
    qkv.A[0] = inr;           qkv.A[1] = inr + IN;      qkv.A[2] = inr + 2 * IN;
    qkv.W[0] = wr;            qkv.W[1] = wr + WSZ;      qkv.W[2] = wr + 2 * WSZ;
    qkv.bias[0] = bq;         qkv.bias[1] = bk;         qkv.bias[2] = bv;
    qkv.out[0] = qb;          qkv.out[1] = kb;          qkv.out[2] = vb;
    qkv.scale[0] = 0.125f * 1.4426950408889634f;        // D^-0.5 * log2(e)
    qkv.scale[1] = 1.0f;      qkv.scale[2] = 1.0f;

    dim3 gqkv(E_DIM / 128, M_DIM / 128, 3);   // (8, 32, 3)
    gemm_kernel<0><<<gqkv, 128, gemm_smem>>>(qkv);

    dim3 gattn(T_DIM / 256, B_DIM * H_DIM);   // (8, 32)
    attn_kernel<<<gattn, 256, attn_smem>>>(qb, kb, vb, bb, ab);

    GemmArgs oargs;
    oargs.A[0] = ab;   oargs.W[0] = wr + 3 * WSZ;  oargs.bias[0] = bo;
    oargs.out[0] = out; oargs.scale[0] = 1.0f;
    oargs.A[1] = oargs.A[2] = ab; oargs.W[1] = oargs.W[2] = wr;
    oargs.bias[1] = oargs.bias[2] = bo; oargs.out[1] = oargs.out[2] = out;
    oargs.scale[1] = oargs.scale[2] = 1.0f;

    dim3 gop(E_DIM / 128, M_DIM / 128, 1);    // (8, 32)
    gemm_kernel<1><<<gop, 128, gemm_smem>>>(oargs);
}

// round 11
// speedup vs baseline: 4.4107x; 1.8502x over previous
#include <cuda_runtime.h>
#include <cuda_fp16.h>
#include <cstdint>

#define T_DIM 2048
#define B_DIM 2
#define E_DIM 1024
#define H_DIM 16
#define D_DIM 64
#define M_DIM (T_DIM * B_DIM)

__device__ __half g_q[B_DIM * H_DIM * T_DIM * D_DIM];
__device__ __half g_k[B_DIM * H_DIM * T_DIM * D_DIM];
__device__ __half g_v[B_DIM * H_DIM * T_DIM * D_DIM];
__device__ __half g_attn[T_DIM * B_DIM * E_DIM];
__device__ float  g_bias[B_DIM * T_DIM];
__device__ __half g_in_h[3 * M_DIM * E_DIM];   // fp16 query|key|value
__device__ __half g_w_h[4 * E_DIM * E_DIM];    // fp16 wq|wk|wv|wo

__device__ __forceinline__ float ex2f(float x) {
    float y;
    asm("ex2.approx.f32 %0, %1;" : "=f"(y) : "f"(x));
    return y;
}

__device__ __forceinline__ void cp16h(__half* smem, const __half* gmem) {
    unsigned s = (unsigned)__cvta_generic_to_shared(smem);
    asm volatile("cp.async.cg.shared.global [%0], [%1], 16;\n" :: "r"(s), "l"(gmem));
}
__device__ __forceinline__ void cp_commit() { asm volatile("cp.async.commit_group;\n"); }
template <int N> __device__ __forceinline__ void cp_wait() {
    asm volatile("cp.async.wait_group %0;\n" :: "n"(N));
}

// fp16 mma with fp32 accumulate: D(16x8) += A(16x16) * B(16x8)
__device__ __forceinline__ void mma16(float* d, const unsigned* a, unsigned b0, unsigned b1) {
    asm volatile(
        "mma.sync.aligned.m16n8k16.row.col.f32.f16.f16.f32 "
        "{%0,%1,%2,%3},{%4,%5,%6,%7},{%8,%9},{%0,%1,%2,%3};"
        : "+f"(d[0]), "+f"(d[1]), "+f"(d[2]), "+f"(d[3])
        : "r"(a[0]), "r"(a[1]), "r"(a[2]), "r"(a[3]), "r"(b0), "r"(b1));
}

__device__ __forceinline__ unsigned ldh2(const __half* p) {
    return *(const unsigned*)p;
}

// ---------------------------------------------------------------------------
// fp32 -> fp16 convert of all GEMM operands
// ---------------------------------------------------------------------------
__global__ void tohalf_kernel(const float4* __restrict__ q, const float4* __restrict__ k,
                              const float4* __restrict__ v, const float4* __restrict__ wq,
                              const float4* __restrict__ wk, const float4* __restrict__ wv,
                              const float4* __restrict__ wo, __half* __restrict__ din,
                              __half* __restrict__ dw)
{
    const int IN4 = M_DIM * E_DIM / 4;
    const int W4  = E_DIM * E_DIM / 4;
    int i = blockIdx.x * blockDim.x + threadIdx.x;
    const float4* s;
    __half* d;
    if (i < 3 * IN4) {
        s = (i < IN4) ? q + i : (i < 2 * IN4 ? k + (i - IN4) : v + (i - 2 * IN4));
        d = din + (size_t)i * 4;
    } else {
        int j = i - 3 * IN4;
        s = (j < W4) ? wq + j : j < 2 * W4 ? wk + (j - W4) : j < 3 * W4 ? wv + (j - 2 * W4)
                                                                        : wo + (j - 3 * W4);
        d = dw + (size_t)j * 4;
    }
    float4 x = *s;
    __half2 h01 = __floats2half2_rn(x.x, x.y);
    __half2 h23 = __floats2half2_rn(x.z, x.w);
    uint2 u;
    u.x = *(unsigned*)&h01;
    u.y = *(unsigned*)&h23;
    *(uint2*)d = u;
}

// bias pre-scaled by log2e (softmax runs in log2 domain)
__global__ void mask_bias_kernel(const unsigned char* __restrict__ mask, float* __restrict__ bias) {
    int i = blockIdx.x * blockDim.x + threadIdx.x;
    if (i < B_DIM * T_DIM) bias[i] = mask[i] ? -1.4426950e30f : 0.0f;
}

// ---------------------------------------------------------------------------
// fp16 GEMM: C[M,1024] = A[M,1024] @ W[1024,1024]^T + bias, * scale
// 128x128 block, 64x64 warp tile (4 warps), BK=32 halfs, 3-stage cp.async,
// m16n8k16 fp16 mma, fp32 accum, register epilogue.
// MODE 0: z picks QKV, writes half to (b,h,t,d). MODE 1: fp32 (row,col).
// ---------------------------------------------------------------------------
struct GemmArgs {
    const __half* A[3];
    const __half* W[3];
    const float* bias[3];
    void* out[3];
    float scale[3];
};

#define GPADH   40                    // halfs per row (32 + 8 pad) = 80 B
#define GSTAGEH (128 * GPADH)         // halfs per matrix tile per stage

template <int MODE>
__global__ __launch_bounds__(128, 2)
void gemm_kernel(GemmArgs args)
{
    extern __shared__ __half smh[];   // 3 stages * 2 * GSTAGEH halfs = 61440 B

    const int z    = (MODE == 0) ? blockIdx.z : 0;
    const __half* A = args.A[z];
    const __half* W = args.W[z];
    const float* bias = args.bias[z];
    const float scale = args.scale[z];

    const int tid  = threadIdx.x;
    const int warp = tid >> 5;
    const int lane = tid & 31;
    const int g    = lane >> 2;
    const int tig  = lane & 3;
    const int wm   = warp >> 1;
    const int wn   = warp & 1;
    const int row0 = blockIdx.y * 128;
    const int col0 = blockIdx.x * 128;

    float acc[4][8][4];
    #pragma unroll
    for (int mi = 0; mi < 4; mi++)
        #pragma unroll
        for (int ni = 0; ni < 8; ni++)
            acc[mi][ni][0] = acc[mi][ni][1] = acc[mi][ni][2] = acc[mi][ni][3] = 0.0f;

    const __half* Agb = &A[(size_t)(row0 + tid) * 1024];
    const __half* Wgb = &W[(size_t)(col0 + tid) * 1024];

    auto stage = [&](int kt, int st) {
        __half* Ad = smh + st * 2 * GSTAGEH + tid * GPADH;
        __half* Bd = Ad + GSTAGEH;
        const int k0 = kt * 32;
        #pragma unroll
        for (int c = 0; c < 32; c += 8) {
            cp16h(Ad + c, Agb + k0 + c);
            cp16h(Bd + c, Wgb + k0 + c);
        }
        cp_commit();
    };

    auto compute = [&](int st) {
        const __half* As = smh + st * 2 * GSTAGEH;
        const __half* Bs = As + GSTAGEH;
        #pragma unroll
        for (int kc = 0; kc < 2; kc++) {
            unsigned af[4][4];
            unsigned bf[8][2];
            #pragma unroll
            for (int mi = 0; mi < 4; mi++) {
                const __half* ap = &As[(wm * 64 + mi * 16) * GPADH + kc * 16];
                af[mi][0] = ldh2(&ap[g * GPADH + 2 * tig]);
                af[mi][1] = ldh2(&ap[(g + 8) * GPADH + 2 * tig]);
                af[mi][2] = ldh2(&ap[g * GPADH + 2 * tig + 8]);
                af[mi][3] = ldh2(&ap[(g + 8) * GPADH + 2 * tig + 8]);
            }
            #pragma unroll
            for (int ni = 0; ni < 8; ni++) {
                const __half* bp = &Bs[(wn * 64 + ni * 8 + g) * GPADH + kc * 16];
                bf[ni][0] = ldh2(&bp[2 * tig]);
                bf[ni][1] = ldh2(&bp[2 * tig + 8]);
            }
            #pragma unroll
            for (int mi = 0; mi < 4; mi++)
                #pragma unroll
                for (int ni = 0; ni < 8; ni++)
                    mma16(acc[mi][ni], af[mi], bf[ni][0], bf[ni][1]);
        }
    };

    const int NT = 1024 / 32;   // 32
    stage(0, 0);
    stage(1, 1);
    for (int t = 0; t < NT; t++) {
        if (t + 1 < NT) cp_wait<1>();
        else            cp_wait<0>();
        __syncthreads();
        if (t + 2 < NT) stage(t + 2, (t + 2) % 3);
        compute(t % 3);
    }

    float bvals[8][2];
    #pragma unroll
    for (int ni = 0; ni < 8; ni++) {
        int c = col0 + wn * 64 + ni * 8 + 2 * tig;
        bvals[ni][0] = __ldg(&bias[c]);
        bvals[ni][1] = __ldg(&bias[c + 1]);
    }
    #pragma unroll
    for (int mi = 0; mi < 4; mi++) {
        #pragma unroll
        for (int rr = 0; rr < 2; rr++) {
            int r = row0 + wm * 64 + mi * 16 + g + rr * 8;   // = t*B + b
            #pragma unroll
            for (int ni = 0; ni < 8; ni++) {
                int o = col0 + wn * 64 + ni * 8 + 2 * tig;
                float v0 = (acc[mi][ni][rr * 2]     + bvals[ni][0]) * scale;
                float v1 = (acc[mi][ni][rr * 2 + 1] + bvals[ni][1]) * scale;
                if (MODE == 0) {
                    __half* out = (__half*)args.out[z];
                    int t = r >> 1, b = r & 1;
                    int h = o >> 6, d = o & 63;
                    *(__half2*)&out[(((size_t)(b * H_DIM + h)) * T_DIM + t) * D_DIM + d] =
                        __floats2half2_rn(v0, v1);
                } else {
                    float* out = (float*)args.out[z];
                    *(float2*)&out[(size_t)r * E_DIM + o] = make_float2(v0, v1);
                }
            }
        }
    }
}

// ---------------------------------------------------------------------------
// Flash attention fp16: 256 threads (8 warps x 32 q), 64-key tiles x 32 iters,
// double-buffered K/V (half), Q frags in regs, V via ldmatrix.x2.trans,
// log2-domain softmax in fp32.
// ---------------------------------------------------------------------------
#define KSTR 72   // halfs per K row (64 + 8) = 144 B
#define VSTR 72
#define PSTR 72

#define ATTN_SMEM_HALFS (2 * 64 * KSTR + 2 * 64 * VSTR + 8 * 32 * PSTR)

__global__ __launch_bounds__(256, 1)
void attn_kernel(const __half* __restrict__ q, const __half* __restrict__ k,
                 const __half* __restrict__ v, const float* __restrict__ biasg,
                 __half* __restrict__ out)
{
    extern __shared__ __half smh[];
    __half* Kst = smh;                         // 2 x 64 x KSTR
    __half* Vst = Kst + 2 * 64 * KSTR;         // 2 x 64 x VSTR
    __half* Ps  = Vst + 2 * 64 * VSTR;         // 8 x 32 x PSTR

    const int tid  = threadIdx.x;
    const int warp = tid >> 5;
    const int lane = tid & 31;
    const int g    = lane >> 2;
    const int tig  = lane & 3;
    const int qt0  = blockIdx.x * 256;
    const int bh   = blockIdx.y;
    const int b    = bh >> 4;
    const int h    = bh & 15;

    const __half* qb = q + (size_t)bh * T_DIM * D_DIM;
    const __half* kb = k + (size_t)bh * T_DIM * D_DIM;
    const __half* vb = v + (size_t)bh * T_DIM * D_DIM;
    const float* bg = biasg + (size_t)b * T_DIM;
    __half* Pw = Ps + warp * 32 * PSTR;

    // Q A-fragments from gmem (once per block): kc 0..3 (k=16 each), m 0..1
    unsigned qa[4][2][4];
    {
        const __half* qw = qb + (size_t)(qt0 + warp * 32) * 64;
        #pragma unroll
        for (int kc = 0; kc < 4; kc++)
            #pragma unroll
            for (int m = 0; m < 2; m++) {
                int r0 = m * 16 + g, r1 = r0 + 8;
                qa[kc][m][0] = ldh2(&qw[r0 * 64 + kc * 16 + 2 * tig]);
                qa[kc][m][1] = ldh2(&qw[r1 * 64 + kc * 16 + 2 * tig]);
                qa[kc][m][2] = ldh2(&qw[r0 * 64 + kc * 16 + 2 * tig + 8]);
                qa[kc][m][3] = ldh2(&qw[r1 * 64 + kc * 16 + 2 * tig + 8]);
            }
    }

    float o[8][2][4];
    #pragma unroll
    for (int dj = 0; dj < 8; dj++)
        #pragma unroll
        for (int m = 0; m < 2; m++)
            o[dj][m][0] = o[dj][m][1] = o[dj][m][2] = o[dj][m][3] = 0.0f;
    float mr[4] = {-1e30f, -1e30f, -1e30f, -1e30f};
    float lr[4] = {0.0f, 0.0f, 0.0f, 0.0f};

    auto stageKV = [&](int it, int buf) {
        const int s0 = it * 64;
        __half* Kd = Kst + buf * 64 * KSTR;
        __half* Vd = Vst + buf * 64 * VSTR;
        #pragma unroll
        for (int i = 0; i < 2; i++) {
            int idx = tid + i * 256;          // 0..511
            int r = idx >> 3, c = (idx & 7) * 8;
            cp16h(&Kd[r * KSTR + c], &kb[(size_t)(s0 + r) * 64 + c]);
            cp16h(&Vd[r * VSTR + c], &vb[(size_t)(s0 + r) * 64 + c]);
        }
        cp_commit();
    };

    const unsigned vst_base = (unsigned)__cvta_generic_to_shared(Vst);

    stageKV(0, 0);
    for (int it = 0; it < 32; it++) {
        cp_wait<0>();
        __syncthreads();
        if (it + 1 < 32) stageKV(it + 1, (it + 1) & 1);

        const __half* Ks = Kst + (it & 1) * 64 * KSTR;
        const unsigned vsb = vst_base + (it & 1) * 64 * VSTR * 2;

        // S = Q @ K^T (per warp 32q x 64k): kc 0..3, j 0..7
        float s[8][2][4];
        #pragma unroll
        for (int j = 0; j < 8; j++)
            #pragma unroll
            for (int m = 0; m < 2; m++)
                s[j][m][0] = s[j][m][1] = s[j][m][2] = s[j][m][3] = 0.0f;
        #pragma unroll
        for (int kc = 0; kc < 4; kc++)
            #pragma unroll
            for (int j = 0; j < 8; j++) {
                const __half* kp = &Ks[(j * 8 + g) * KSTR + kc * 16];
                unsigned b0 = ldh2(&kp[2 * tig]);
                unsigned b1 = ldh2(&kp[2 * tig + 8]);
                #pragma unroll
                for (int m = 0; m < 2; m++) mma16(s[j][m], qa[kc][m], b0, b1);
            }

        // Online softmax (log2 domain); 4 row states per thread
        float vmax[4] = {-1e30f, -1e30f, -1e30f, -1e30f};
        #pragma unroll
        for (int j = 0; j < 8; j++) {
            float b0v = __ldg(&bg[it * 64 + j * 8 + 2 * tig]);
            float b1v = __ldg(&bg[it * 64 + j * 8 + 2 * tig + 1]);
            #pragma unroll
            for (int m = 0; m < 2; m++) {
                s[j][m][0] += b0v; s[j][m][1] += b1v;
                s[j][m][2] += b0v; s[j][m][3] += b1v;
                vmax[m * 2]     = fmaxf(vmax[m * 2],     fmaxf(s[j][m][0], s[j][m][1]));
                vmax[m * 2 + 1] = fmaxf(vmax[m * 2 + 1], fmaxf(s[j][m][2], s[j][m][3]));
            }
        }
        float al[4], sum[4];
        #pragma unroll
        for (int st = 0; st < 4; st++) {
            vmax[st] = fmaxf(vmax[st], __shfl_xor_sync(0xffffffffu, vmax[st], 1));
            vmax[st] = fmaxf(vmax[st], __shfl_xor_sync(0xffffffffu, vmax[st], 2));
            float mn = fmaxf(mr[st], vmax[st]);
            al[st] = ex2f(mr[st] - mn);
            mr[st] = mn;
            sum[st] = 0.0f;
        }
        #pragma unroll
        for (int j = 0; j < 8; j++)
            #pragma unroll
            for (int m = 0; m < 2; m++) {
                s[j][m][0] = ex2f(s[j][m][0] - mr[m * 2]);     sum[m * 2]     += s[j][m][0];
                s[j][m][1] = ex2f(s[j][m][1] - mr[m * 2]);     sum[m * 2]     += s[j][m][1];
                s[j][m][2] = ex2f(s[j][m][2] - mr[m * 2 + 1]); sum[m * 2 + 1] += s[j][m][2];
                s[j][m][3] = ex2f(s[j][m][3] - mr[m * 2 + 1]); sum[m * 2 + 1] += s[j][m][3];
            }
        #pragma unroll
        for (int st = 0; st < 4; st++) {
            sum[st] += __shfl_xor_sync(0xffffffffu, sum[st], 1);
            sum[st] += __shfl_xor_sync(0xffffffffu, sum[st], 2);
            lr[st] = lr[st] * al[st] + sum[st];
        }
        #pragma unroll
        for (int dj = 0; dj < 8; dj++)
            #pragma unroll
            for (int m = 0; m < 2; m++) {
                o[dj][m][0] *= al[m * 2];     o[dj][m][1] *= al[m * 2];
                o[dj][m][2] *= al[m * 2 + 1]; o[dj][m][3] *= al[m * 2 + 1];
            }

        // P acc-layout -> half in per-warp smem
        #pragma unroll
        for (int j = 0; j < 8; j++)
            #pragma unroll
            for (int m = 0; m < 2; m++) {
                *(__half2*)&Pw[(m * 16 + g) * PSTR + j * 8 + 2 * tig] =
                    __floats2half2_rn(s[j][m][0], s[j][m][1]);
                *(__half2*)&Pw[(m * 16 + g + 8) * PSTR + j * 8 + 2 * tig] =
                    __floats2half2_rn(s[j][m][2], s[j][m][3]);
            }
        __syncwarp();

        // O += P @ V: kc 0..3 (key chunks of 16), dj 0..7 (d tiles of 8)
        #pragma unroll
        for (int kc = 0; kc < 4; kc++) {
            unsigned pa[2][4];
            #pragma unroll
            for (int m = 0; m < 2; m++) {
                const __half* pp = &Pw[(m * 16 + g) * PSTR + kc * 16];
                pa[m][0] = ldh2(&pp[2 * tig]);
                pa[m][1] = ldh2(&pp[8 * PSTR + 2 * tig]);
                pa[m][2] = ldh2(&pp[2 * tig + 8]);
                pa[m][3] = ldh2(&pp[8 * PSTR + 2 * tig + 8]);
            }
            // ldmatrix base: row = kc*16 + (lane&15), col 0 (dj adds 16B)
            unsigned vaddr = vsb + (kc * 16 + (lane & 15)) * (VSTR * 2);
            #pragma unroll
            for (int dj = 0; dj < 8; dj++) {
                unsigned b0, b1;
                asm volatile(
                    "ldmatrix.sync.aligned.m8n8.x2.trans.shared.b16 {%0,%1}, [%2];"
                    : "=r"(b0), "=r"(b1) : "r"(vaddr + dj * 16));
                #pragma unroll
                for (int m = 0; m < 2; m++) mma16(o[dj][m], pa[m], b0, b1);
            }
        }
        __syncthreads();   // V/K buffer reuse + Pw reuse next iteration
    }

    // Epilogue: out[(t,b), h*64 + d] = O / l  (half)
    #pragma unroll
    for (int m = 0; m < 2; m++) {
        float i0 = (lr[m * 2] > 0.0f)     ? 1.0f / lr[m * 2]     : 0.0f;
        float i1 = (lr[m * 2 + 1] > 0.0f) ? 1.0f / lr[m * 2 + 1] : 0.0f;
        int t0 = qt0 + warp * 32 + m * 16 + g;
        int t1 = t0 + 8;
        __half* d0 = out + ((size_t)t0 * B_DIM + b) * E_DIM + h * 64;
        __half* d1 = out + ((size_t)t1 * B_DIM + b) * E_DIM + h * 64;
        #pragma unroll
        for (int dj = 0; dj < 8; dj++) {
            *(__half2*)&d0[dj * 8 + 2 * tig] =
                __floats2half2_rn(o[dj][m][0] * i0, o[dj][m][1] * i0);
            *(__half2*)&d1[dj * 8 + 2 * tig] =
                __floats2half2_rn(o[dj][m][2] * i1, o[dj][m][3] * i1);
        }
    }
}

// ---------------------------------------------------------------------------
extern "C" void kernel_launch(void* const* d_in, const int* in_sizes, int n_in,
                              void* d_out, int out_size)
{
    (void)in_sizes; (void)n_in; (void)out_size;
    const float* query = (const float*)d_in[0];
    const float* key   = (const float*)d_in[1];
    const float* value = (const float*)d_in[2];
    const unsigned char* mask = (const unsigned char*)d_in[3];
    const float* wq = (const float*)d_in[4];
    const float* bq = (const float*)d_in[5];
    const float* wk = (const float*)d_in[6];
    const float* bk = (const float*)d_in[7];
    const float* wv = (const float*)d_in[8];
    const float* bv = (const float*)d_in[9];
    const float* wo = (const float*)d_in[10];
    const float* bo = (const float*)d_in[11];
    float* out = (float*)d_out;

    __half *qb, *kb, *vb, *ab, *inh, *wh;
    float *bb;
    cudaGetSymbolAddress((void**)&qb, g_q);
    cudaGetSymbolAddress((void**)&kb, g_k);
    cudaGetSymbolAddress((void**)&vb, g_v);
    cudaGetSymbolAddress((void**)&ab, g_attn);
    cudaGetSymbolAddress((void**)&bb, g_bias);
    cudaGetSymbolAddress((void**)&inh, g_in_h);
    cudaGetSymbolAddress((void**)&wh, g_w_h);

    const int IN  = M_DIM * E_DIM;
    const int WSZ = E_DIM * E_DIM;

    static int smem_set = 0;
    const int gemm_smem = 3 * 2 * GSTAGEH * (int)sizeof(__half);   // 61440
    const int attn_smem = ATTN_SMEM_HALFS * (int)sizeof(__half);   // 73728
    if (!smem_set) {
        cudaFuncSetAttribute(gemm_kernel<0>, cudaFuncAttributeMaxDynamicSharedMemorySize, gemm_smem);
        cudaFuncSetAttribute(gemm_kernel<1>, cudaFuncAttributeMaxDynamicSharedMemorySize, gemm_smem);
        cudaFuncSetAttribute(attn_kernel, cudaFuncAttributeMaxDynamicSharedMemorySize, attn_smem);
        smem_set = 1;
    }

    tohalf_kernel<<<(3 * IN + 4 * WSZ) / 4 / 256, 256>>>(
        (const float4*)query, (const float4*)key, (const float4*)value,
        (const float4*)wq, (const float4*)wk, (const float4*)wv, (const float4*)wo,
        inh, wh);

    mask_bias_kernel<<<(B_DIM * T_DIM + 255) / 256, 256>>>(mask, bb);

    GemmArgs qkv;
    qkv.A[0] = inh;           qkv.A[1] = inh + IN;      qkv.A[2] = inh + 2 * IN;
    qkv.W[0] = wh;            qkv.W[1] = wh + WSZ;      qkv.W[2] = wh + 2 * WSZ;
    qkv.bias[0] = bq;         qkv.bias[1] = bk;         qkv.bias[2] = bv;
    qkv.out[0] = qb;          qkv.out[1] = kb;          qkv.out[2] = vb;
    qkv.scale[0] = 0.125f * 1.4426950408889634f;        // D^-0.5 * log2(e)
    qkv.scale[1] = 1.0f;      qkv.scale[2] = 1.0f;

    dim3 gqkv(E_DIM / 128, M_DIM / 128, 3);   // (8, 32, 3)
    gemm_kernel<0><<<gqkv, 128, gemm_smem>>>(qkv);

    dim3 gattn(T_DIM / 256, B_DIM * H_DIM);   // (8, 32)
    attn_kernel<<<gattn, 256, attn_smem>>>(qb, kb, vb, bb, ab);

    GemmArgs oargs;
    oargs.A[0] = ab;   oargs.W[0] = wh + 3 * WSZ;  oargs.bias[0] = bo;
    oargs.out[0] = out; oargs.scale[0] = 1.0f;
    oargs.A[1] = oargs.A[2] = ab; oargs.W[1] = oargs.W[2] = wh;
    oargs.bias[1] = oargs.bias[2] = bo; oargs.out[1] = oargs.out[2] = (void*)out;
    oargs.scale[1] = oargs.scale[2] = 1.0f;

    dim3 gop(E_DIM / 128, M_DIM / 128, 1);    // (8, 32)
    gemm_kernel<1><<<gop, 128, gemm_smem>>>(oargs);
}